// round 13
// baseline (speedup 1.0000x reference)
#include <cuda_runtime.h>
#include <cstdint>

// PhysicsAttention: N=64, C=128, T=256, V=25, O=128
// Round 13: R12 math + ldmatrix fragment loads (16B-atomic swizzle), uint4 weight
// B-loads (2 MMAs per LDG), merged G accumulators, div-free store loop.

#define NT_TOTAL 16384

__device__ uint32_t g_Wf[24576];  // fp16 frag images (ks-major): Mhi | Mlo | Vf16 (8192 u32 each)
__device__ float g_u[128];
__device__ float g_bias[25 * 26];

// ---------------- helpers ----------------
__device__ __forceinline__ unsigned short f2h(float f) {
    unsigned short u;
    asm("cvt.rn.f16.f32 %0, %1;" : "=h"(u) : "f"(f));
    return u;
}
__device__ __forceinline__ float h2f(unsigned short u) {
    float f;
    asm("cvt.f32.f16 %0, %1;" : "=f"(f) : "h"(u));
    return f;
}
__device__ __forceinline__ uint32_t packh(float a, float b) {
    return (uint32_t)f2h(a) | ((uint32_t)f2h(b) << 16);
}
__device__ __forceinline__ void split2(float x0, float x1, uint32_t& hi, uint32_t& lo) {
    unsigned short h0 = f2h(x0), h1 = f2h(x1);
    hi = (uint32_t)h0 | ((uint32_t)h1 << 16);
    lo = packh(x0 - h2f(h0), x1 - h2f(h1));
}
__device__ __forceinline__ uint32_t smem_u32(const void* p) {
    uint32_t a;
    asm("{ .reg .u64 t; cvta.to.shared.u64 t, %1; cvt.u32.u64 %0, t; }" : "=r"(a) : "l"(p));
    return a;
}

#define MMA_F16(d, a, b0v, b1v)                                                   \
    asm("mma.sync.aligned.m16n8k16.row.col.f32.f16.f16.f32 "                      \
        "{%0,%1,%2,%3},{%4,%5,%6,%7},{%8,%9},{%0,%1,%2,%3};"                      \
        : "+f"((d)[0]), "+f"((d)[1]), "+f"((d)[2]), "+f"((d)[3])                  \
        : "r"((a)[0]), "r"((a)[1]), "r"((a)[2]), "r"((a)[3]), "r"(b0v), "r"(b1v))

#define LDSM_X4(r0, r1, r2, r3, addr)                                             \
    asm volatile("ldmatrix.sync.aligned.m8n8.x4.shared.b16 {%0,%1,%2,%3}, [%4];"  \
                 : "=r"(r0), "=r"(r1), "=r"(r2), "=r"(r3) : "r"(addr))

// X-image: [row 0..31][u32 kp 0..63], 16B-atomic swizzle: block b = kp>>2,
// u32 idx = row*64 + ((b ^ (row&7))<<2) + (kp&3). LDSM-phase and STS.128 conflict-free.
__device__ __forceinline__ int aidx16(int row, int kp) {
    return row * 64 + ((((kp >> 2) ^ (row & 7)) << 2) | (kp & 3));
}

// ---------------- precompute: frag-ordered fp16 weight images (ks-major), u, bias ----------
__global__ void precompute_kernel(const float* __restrict__ wq,
                                  const float* __restrict__ bq,
                                  const float* __restrict__ wk,
                                  const float* __restrict__ wv,
                                  const float* __restrict__ bias_emb,
                                  const int* __restrict__ hop) {
    const float inv = 0.088388347648318447f;  // 1/sqrt(128)
    int b = blockIdx.x, k = threadIdx.x;
    if (b < 128) {
        const int n = b;
        float m = 0.f;
#pragma unroll 8
        for (int o = 0; o < 128; o++) m += wq[o * 128 + k] * wk[o * 128 + n];
        m *= inv;
        float wvv = wv[n * 128 + k];
        // fragment position for m16n8k16 B (col) operand, ks-major + nt-adjacent layout
        const int nt = n >> 3, j = n & 7, i = k & 15, ks = k >> 4;
        const int lane = j * 4 + ((i & 7) >> 1);
        const int reg = i >> 3;
        const int half = i & 1;
        const int u32idx = ((ks * 32 + lane) * 16 + nt) * 2 + reg;
        unsigned short* B16 = (unsigned short*)g_Wf;
        unsigned short mh = f2h(m);
        B16[(0 * 8192 + u32idx) * 2 + half] = mh;                // Mhi
        B16[(1 * 8192 + u32idx) * 2 + half] = f2h(m - h2f(mh));  // Mlo
        B16[(2 * 8192 + u32idx) * 2 + half] = f2h(wvv);          // Vf16
    } else if (b == 128) {
        float uu = 0.f;
#pragma unroll 8
        for (int o = 0; o < 128; o++) uu += bq[o] * wk[o * 128 + k];
        g_u[k] = uu * inv;
    } else {
        for (int i = k; i < 625; i += 128) {
            int v = i / 25, w = i - v * 25;
            g_bias[v * 26 + w] = bias_emb[hop[i]];
        }
    }
}

// ---------------- fused kernel: 8 warps/CTA, warp-pair per tile, 4 tiles/CTA ----------------
// smem: 4 x (X hi/lo image 16KB) = 65536 B -> 2 CTAs/SM
extern __shared__ uint32_t sm[];

__global__ __launch_bounds__(256, 2) void fused_kernel(const float* __restrict__ x,
                                                       const float* __restrict__ bv,
                                                       float* __restrict__ out) {
    const int tid = threadIdx.x;
    const int lane = tid & 31;
    const int w = tid >> 5;
    const int mh = w & 1;   // m-half within the tile
    const int tp = w >> 1;  // tile slot 0..3
    const int g = lane >> 2, tc = lane & 3;

    uint32_t* Xhi = sm + tp * 4096;  // 2048 u32
    uint32_t* Xlo = Xhi + 2048;      // 2048 u32

    const int tile = blockIdx.x * 4 + tp;
    const int n = tile >> 8;
    const int t = tile & 255;
    const long xbase = (long)n * 819200 + (long)t * 25;

    // ---- x tile -> fp16 hi/lo images; pair splits block range (lane = row v) ----
    {
        const bool valid = lane < 25;
        const float* xr = x + xbase + lane;
        uint4* Xhi4 = (uint4*)Xhi;
        uint4* Xlo4 = (uint4*)Xlo;
        const int f = lane & 7;
#pragma unroll 2
        for (int j = 0; j < 8; j++) {
            const int b = mh * 8 + j;  // 16B block = 4 u32 = 8 channels
            const float* xb = xr + (long)b * 51200;
            uint4 hi4, lo4;
            float x0, x1;
            x0 = valid ? __ldcs(xb + 0) : 0.f;
            x1 = valid ? __ldcs(xb + 6400) : 0.f;
            split2(x0, x1, hi4.x, lo4.x);
            x0 = valid ? __ldcs(xb + 12800) : 0.f;
            x1 = valid ? __ldcs(xb + 19200) : 0.f;
            split2(x0, x1, hi4.y, lo4.y);
            x0 = valid ? __ldcs(xb + 25600) : 0.f;
            x1 = valid ? __ldcs(xb + 32000) : 0.f;
            split2(x0, x1, hi4.z, lo4.z);
            x0 = valid ? __ldcs(xb + 38400) : 0.f;
            x1 = valid ? __ldcs(xb + 44800) : 0.f;
            split2(x0, x1, hi4.w, lo4.w);
            const int i4 = lane * 16 + (b ^ f);
            Xhi4[i4] = hi4;
            Xlo4[i4] = lo4;
        }
    }
    __syncthreads();

    const int row0 = 16 * mh;
    const uint32_t XhiA = smem_u32(Xhi);
    const uint32_t XloA = XhiA + 8192;

    // A-frag LDSM address components (rows row0..row0+15)
    const int rowA = row0 + (lane & 7) + 8 * ((lane >> 3) & 1);
    const uint32_t AoffRow = (uint32_t)rowA * 256;
    const int fA = rowA & 7;
    const int kbA = (lane >> 4) & 1;

    // ---- G = X*M (+u), 3-pass fp16 split, merged acc[16] ----
    float acc[16][4];
#pragma unroll
    for (int nt = 0; nt < 16; nt++)
#pragma unroll
        for (int q = 0; q < 4; q++) acc[nt][q] = 0.f;
#pragma unroll 1
    for (int pass = 0; pass < 3; pass++) {
        const uint32_t Abase = ((pass == 2) ? XloA : XhiA) + AoffRow;
        const uint4* Bp = (const uint4*)g_Wf + ((pass == 1) ? 2048 : 0) + lane * 8;
#pragma unroll
        for (int ks = 0; ks < 8; ks++) {
            uint32_t a[4];
            LDSM_X4(a[0], a[1], a[2], a[3],
                    Abase + (uint32_t)((((2 * ks + kbA) ^ fA)) << 4));
#pragma unroll
            for (int nt2 = 0; nt2 < 8; nt2++) {
                const uint4 b = __ldg(Bp + ks * 256 + nt2);
                MMA_F16(acc[2 * nt2], a, b.x, b.y);
                MMA_F16(acc[2 * nt2 + 1], a, b.z, b.w);
            }
        }
    }

    // ---- +u, convert G into A-fragments (acc layout == A-frag layout) ----
    uint32_t GhA[8][4], GlA[8][4];
#pragma unroll
    for (int kk = 0; kk < 8; kk++) {
        float2 ua = *(const float2*)(g_u + 16 * kk + 2 * tc);
        float2 ub = *(const float2*)(g_u + 16 * kk + 8 + 2 * tc);
        float v00 = acc[2 * kk][0] + ua.x, v01 = acc[2 * kk][1] + ua.y;
        float v10 = acc[2 * kk][2] + ua.x, v11 = acc[2 * kk][3] + ua.y;
        float v20 = acc[2 * kk + 1][0] + ub.x, v21 = acc[2 * kk + 1][1] + ub.y;
        float v30 = acc[2 * kk + 1][2] + ub.x, v31 = acc[2 * kk + 1][3] + ub.y;
        unsigned short h00 = f2h(v00), h01 = f2h(v01), h10 = f2h(v10), h11 = f2h(v11);
        unsigned short h20 = f2h(v20), h21 = f2h(v21), h30 = f2h(v30), h31 = f2h(v31);
        GhA[kk][0] = (uint32_t)h00 | ((uint32_t)h01 << 16);
        GhA[kk][1] = (uint32_t)h10 | ((uint32_t)h11 << 16);
        GhA[kk][2] = (uint32_t)h20 | ((uint32_t)h21 << 16);
        GhA[kk][3] = (uint32_t)h30 | ((uint32_t)h31 << 16);
        GlA[kk][0] = packh(v00 - h2f(h00), v01 - h2f(h01));
        GlA[kk][1] = packh(v10 - h2f(h10), v11 - h2f(h11));
        GlA[kk][2] = packh(v20 - h2f(h20), v21 - h2f(h21));
        GlA[kk][3] = packh(v30 - h2f(h30), v31 - h2f(h31));
    }

    // ---- S = G * X^T (3-pass), B-frags via LDSM from X images ----
    const int rowS = (lane & 7) + 8 * ((lane >> 4) & 1);
    const uint32_t SoffRow1 = (uint32_t)rowS * 256;
    const uint32_t SoffRow2 = SoffRow1 + 16 * 256;
    const int fS = lane & 7;
    const int kbS = (lane >> 3) & 1;

    float S[4][4];
#pragma unroll
    for (int nt = 0; nt < 4; nt++)
#pragma unroll
        for (int q = 0; q < 4; q++) S[nt][q] = 0.f;
#pragma unroll 1
    for (int pass = 0; pass < 3; pass++) {
        const uint32_t(*Aa)[4] = (pass == 2) ? GlA : GhA;
        const uint32_t Bbase = (pass == 1) ? XloA : XhiA;
#pragma unroll
        for (int ks = 0; ks < 8; ks++) {
            const uint32_t off = (uint32_t)(((2 * ks + kbS) ^ fS) << 4);
            uint32_t b0, b1, b2, b3, c0, c1, c2, c3;
            LDSM_X4(b0, b1, b2, b3, Bbase + SoffRow1 + off);
            LDSM_X4(c0, c1, c2, c3, Bbase + SoffRow2 + off);
            MMA_F16(S[0], Aa[ks], b0, b1);
            MMA_F16(S[1], Aa[ks], b2, b3);
            MMA_F16(S[2], Aa[ks], c0, c1);
            MMA_F16(S[3], Aa[ks], c2, c3);
        }
    }

    // ---- bias + mask + softmax (rows live in 4-lane groups) ----
    {
        const int v0 = row0 + g;
        const int v1c = (v0 + 8 < 25) ? v0 + 8 : 24;  // index clamp only
#pragma unroll
        for (int nt = 0; nt < 4; nt++) {
            const int w0 = 8 * nt + 2 * tc, w1 = w0 + 1;
            if (w0 < 25) {
                S[nt][0] += g_bias[v0 * 26 + w0];
                S[nt][2] += g_bias[v1c * 26 + w0];
            } else {
                S[nt][0] = -1e30f;
                S[nt][2] = -1e30f;
            }
            if (w1 < 25) {
                S[nt][1] += g_bias[v0 * 26 + w1];
                S[nt][3] += g_bias[v1c * 26 + w1];
            } else {
                S[nt][1] = -1e30f;
                S[nt][3] = -1e30f;
            }
        }
    }
#pragma unroll
    for (int h = 0; h < 2; h++) {
        float mx = -1e30f;
#pragma unroll
        for (int nt = 0; nt < 4; nt++)
            mx = fmaxf(mx, fmaxf(S[nt][2 * h], S[nt][2 * h + 1]));
        mx = fmaxf(mx, __shfl_xor_sync(0xffffffffu, mx, 1));
        mx = fmaxf(mx, __shfl_xor_sync(0xffffffffu, mx, 2));
        float sum = 0.f;
#pragma unroll
        for (int nt = 0; nt < 4; nt++) {
            float e0 = __expf(S[nt][2 * h] - mx);
            float e1 = __expf(S[nt][2 * h + 1] - mx);
            S[nt][2 * h] = e0;
            S[nt][2 * h + 1] = e1;
            sum += e0 + e1;
        }
        sum += __shfl_xor_sync(0xffffffffu, sum, 1);
        sum += __shfl_xor_sync(0xffffffffu, sum, 2);
        float inv = __fdividef(1.f, sum);
#pragma unroll
        for (int nt = 0; nt < 4; nt++) {
            S[nt][2 * h] *= inv;
            S[nt][2 * h + 1] *= inv;
        }
    }

    // ---- P -> fp16 A-fragments (in-register) ----
    uint32_t PA[2][4];
#pragma unroll
    for (int ks = 0; ks < 2; ks++) {
        PA[ks][0] = packh(S[2 * ks][0], S[2 * ks][1]);
        PA[ks][1] = packh(S[2 * ks][2], S[2 * ks][3]);
        PA[ks][2] = packh(S[2 * ks + 1][0], S[2 * ks + 1][1]);
        PA[ks][3] = packh(S[2 * ks + 1][2], S[2 * ks + 1][3]);
    }

    // ---- V = X * wv^T, single-pass fp16 (A via LDSM from Xhi, B uint4 via L1) ----
    float accV[16][4];
#pragma unroll
    for (int nt = 0; nt < 16; nt++)
#pragma unroll
        for (int q = 0; q < 4; q++) accV[nt][q] = 0.f;
    {
        const uint32_t Abase = XhiA + AoffRow;
        const uint4* Bp = (const uint4*)g_Wf + 4096 + lane * 8;
#pragma unroll
        for (int ks = 0; ks < 8; ks++) {
            uint32_t a[4];
            LDSM_X4(a[0], a[1], a[2], a[3],
                    Abase + (uint32_t)((((2 * ks + kbA) ^ fA)) << 4));
#pragma unroll
            for (int nt2 = 0; nt2 < 8; nt2++) {
                const uint4 b = __ldg(Bp + ks * 256 + nt2);
                MMA_F16(accV[2 * nt2], a, b.x, b.y);
                MMA_F16(accV[2 * nt2 + 1], a, b.z, b.w);
            }
        }
    }
    __syncthreads();  // all warps done reading X images

    // ---- Vso overlay: V^T fp16 [o][w], fp16 row stride 40 (u32 stride 20) ----
    unsigned short* Vso = (unsigned short*)Xhi;  // 2560 u32 < 4096 (tile region)
#pragma unroll
    for (int nt = 0; nt < 16; nt++) {
        const int r0 = row0 + g, o0 = 8 * nt + 2 * tc;
        Vso[o0 * 40 + r0] = f2h(accV[nt][0]);
        Vso[(o0 + 1) * 40 + r0] = f2h(accV[nt][1]);
        Vso[o0 * 40 + r0 + 8] = f2h(accV[nt][2]);
        Vso[(o0 + 1) * 40 + r0 + 8] = f2h(accV[nt][3]);
    }
    __syncthreads();

    // ---- PV: out[v][o] = P*V via MMA (k = w padded to 32; pads exact zeros) ----
    float accO[16][4];
#pragma unroll
    for (int nt = 0; nt < 16; nt++) {
        float2 bb = *(const float2*)(bv + 8 * nt + 2 * tc);
        accO[nt][0] = bb.x;
        accO[nt][1] = bb.y;
        accO[nt][2] = bb.x;
        accO[nt][3] = bb.y;
    }
    {
        const uint32_t* VsoU = (const uint32_t*)Vso;
#pragma unroll
        for (int ks = 0; ks < 2; ks++) {
#pragma unroll
            for (int nt = 0; nt < 16; nt++) {
                const int orow = (8 * nt + g) * 20;
                uint32_t b0 = VsoU[orow + 8 * ks + tc];
                uint32_t b1 = VsoU[orow + 8 * ks + 4 + tc];
                MMA_F16(accO[nt], PA[ks], b0, b1);
            }
        }
    }
    __syncthreads();  // PV reads of Vso done before overwrite

    // ---- stage outs[o][v] (overwrite tile region), then coalesced store ----
    float* outs = (float*)Xhi;  // 128*26 floats = 3328 u32 < 4096
    {
        const int v0 = row0 + g;
        const int v1 = v0 + 8;
#pragma unroll
        for (int nt = 0; nt < 16; nt++) {
            const int o0 = 8 * nt + 2 * tc;
            outs[o0 * 26 + v0] = accO[nt][0];
            outs[(o0 + 1) * 26 + v0] = accO[nt][1];
            if (v1 < 25) {
                outs[o0 * 26 + v1] = accO[nt][2];
                outs[(o0 + 1) * 26 + v1] = accO[nt][3];
            }
        }
    }
    __syncthreads();

    const long obase = (long)n * 819200 + (long)t * 25;
    {
        int idx = lane + 32 * mh;
        int oo = idx / 25;
        int v = idx - oo * 25;
#pragma unroll 1
        for (int i = 0; i < 50; i++) {
            __stcs(&out[obase + (long)oo * 6400 + v], outs[oo * 26 + v]);
            oo += 2;
            v += 14;
            if (v >= 25) {
                v -= 25;
                oo += 1;
            }
        }
    }
}

extern "C" void kernel_launch(void* const* d_in, const int* in_sizes, int n_in,
                              void* d_out, int out_size) {
    (void)in_sizes; (void)n_in; (void)out_size;
    const float* x = (const float*)d_in[0];
    const float* wq = (const float*)d_in[1];
    const float* bq = (const float*)d_in[2];
    const float* wk = (const float*)d_in[3];
    // d_in[4] = bk: softmax-invariant (row-constant), unused
    const float* wv = (const float*)d_in[5];
    const float* bv = (const float*)d_in[6];
    const float* be = (const float*)d_in[7];
    const int* hop = (const int*)d_in[8];

    cudaFuncSetAttribute(fused_kernel, cudaFuncAttributeMaxDynamicSharedMemorySize,
                         65536);

    precompute_kernel<<<130, 128>>>(wq, bq, wk, wv, be, hop);
    fused_kernel<<<NT_TOTAL / 4, 256, 65536>>>(x, bv, (float*)d_out);
}

// round 14
// speedup vs baseline: 3.1458x; 3.1458x over previous
#include <cuda_runtime.h>
#include <cstdint>

// PhysicsAttention: N=64, C=128, T=256, V=25, O=128
// Round 14 = Round 13 with the weight-layout fix: uint4 B-fragments lane-contiguous
// ((ks*8+nt2)*32+lane) so LDG.128 is fully coalesced (R13 had lane-stride-128B -> nL=32).

#define NT_TOTAL 16384

__device__ uint32_t g_Wf[24576];  // fp16 frag images: Mhi | Mlo | Vf16 (8192 u32 each)
__device__ float g_u[128];
__device__ float g_bias[25 * 26];

// ---------------- helpers ----------------
__device__ __forceinline__ unsigned short f2h(float f) {
    unsigned short u;
    asm("cvt.rn.f16.f32 %0, %1;" : "=h"(u) : "f"(f));
    return u;
}
__device__ __forceinline__ float h2f(unsigned short u) {
    float f;
    asm("cvt.f32.f16 %0, %1;" : "=f"(f) : "h"(u));
    return f;
}
__device__ __forceinline__ uint32_t packh(float a, float b) {
    return (uint32_t)f2h(a) | ((uint32_t)f2h(b) << 16);
}
__device__ __forceinline__ void split2(float x0, float x1, uint32_t& hi, uint32_t& lo) {
    unsigned short h0 = f2h(x0), h1 = f2h(x1);
    hi = (uint32_t)h0 | ((uint32_t)h1 << 16);
    lo = packh(x0 - h2f(h0), x1 - h2f(h1));
}
__device__ __forceinline__ uint32_t smem_u32(const void* p) {
    uint32_t a;
    asm("{ .reg .u64 t; cvta.to.shared.u64 t, %1; cvt.u32.u64 %0, t; }" : "=r"(a) : "l"(p));
    return a;
}

#define MMA_F16(d, a, b0v, b1v)                                                   \
    asm("mma.sync.aligned.m16n8k16.row.col.f32.f16.f16.f32 "                      \
        "{%0,%1,%2,%3},{%4,%5,%6,%7},{%8,%9},{%0,%1,%2,%3};"                      \
        : "+f"((d)[0]), "+f"((d)[1]), "+f"((d)[2]), "+f"((d)[3])                  \
        : "r"((a)[0]), "r"((a)[1]), "r"((a)[2]), "r"((a)[3]), "r"(b0v), "r"(b1v))

#define LDSM_X4(r0, r1, r2, r3, addr)                                             \
    asm volatile("ldmatrix.sync.aligned.m8n8.x4.shared.b16 {%0,%1,%2,%3}, [%4];"  \
                 : "=r"(r0), "=r"(r1), "=r"(r2), "=r"(r3) : "r"(addr))

// ---------------- precompute: frag-ordered fp16 weight images, u, bias ----------
__global__ void precompute_kernel(const float* __restrict__ wq,
                                  const float* __restrict__ bq,
                                  const float* __restrict__ wk,
                                  const float* __restrict__ wv,
                                  const float* __restrict__ bias_emb,
                                  const int* __restrict__ hop) {
    const float inv = 0.088388347648318447f;  // 1/sqrt(128)
    int b = blockIdx.x, k = threadIdx.x;
    if (b < 128) {
        const int n = b;
        float m = 0.f;
#pragma unroll 8
        for (int o = 0; o < 128; o++) m += wq[o * 128 + k] * wk[o * 128 + n];
        m *= inv;
        float wvv = wv[n * 128 + k];
        // fragment position for m16n8k16 B (col) operand; uint4-packed nt-pairs,
        // lane-contiguous: u32idx = ((ks*8+nt2)*32+lane)*4 + (nt&1)*2 + reg
        const int nt = n >> 3, j = n & 7, i = k & 15, ks = k >> 4;
        const int lane = j * 4 + ((i & 7) >> 1);
        const int reg = i >> 3;
        const int half = i & 1;
        const int u32idx = (((ks * 8 + (nt >> 1)) * 32 + lane) << 2) + ((nt & 1) << 1) + reg;
        unsigned short* B16 = (unsigned short*)g_Wf;
        unsigned short mh = f2h(m);
        B16[(0 * 8192 + u32idx) * 2 + half] = mh;                // Mhi
        B16[(1 * 8192 + u32idx) * 2 + half] = f2h(m - h2f(mh));  // Mlo
        B16[(2 * 8192 + u32idx) * 2 + half] = f2h(wvv);          // Vf16
    } else if (b == 128) {
        float uu = 0.f;
#pragma unroll 8
        for (int o = 0; o < 128; o++) uu += bq[o] * wk[o * 128 + k];
        g_u[k] = uu * inv;
    } else {
        for (int i = k; i < 625; i += 128) {
            int v = i / 25, w = i - v * 25;
            g_bias[v * 26 + w] = bias_emb[hop[i]];
        }
    }
}

// ---------------- fused kernel: 8 warps/CTA, warp-pair per tile, 4 tiles/CTA ----------------
// smem: 4 x (X hi/lo image 16KB) = 65536 B -> 2 CTAs/SM
extern __shared__ uint32_t sm[];

__global__ __launch_bounds__(256, 2) void fused_kernel(const float* __restrict__ x,
                                                       const float* __restrict__ bv,
                                                       float* __restrict__ out) {
    const int tid = threadIdx.x;
    const int lane = tid & 31;
    const int w = tid >> 5;
    const int mh = w & 1;   // m-half within the tile
    const int tp = w >> 1;  // tile slot 0..3
    const int g = lane >> 2, tc = lane & 3;

    uint32_t* Xhi = sm + tp * 4096;  // 2048 u32
    uint32_t* Xlo = Xhi + 2048;      // 2048 u32

    const int tile = blockIdx.x * 4 + tp;
    const int n = tile >> 8;
    const int t = tile & 255;
    const long xbase = (long)n * 819200 + (long)t * 25;

    // ---- x tile -> fp16 hi/lo images; pair splits block range (lane = row v) ----
    // X-image: [row][16B block b], swizzled: uint4 idx = row*16 + (b ^ (row&7)).
    {
        const bool valid = lane < 25;
        const float* xr = x + xbase + lane;
        uint4* Xhi4 = (uint4*)Xhi;
        uint4* Xlo4 = (uint4*)Xlo;
        const int f = lane & 7;
#pragma unroll 2
        for (int j = 0; j < 8; j++) {
            const int b = mh * 8 + j;  // 16B block = 4 u32 = 8 channels
            const float* xb = xr + (long)b * 51200;
            uint4 hi4, lo4;
            float x0, x1;
            x0 = valid ? __ldcs(xb + 0) : 0.f;
            x1 = valid ? __ldcs(xb + 6400) : 0.f;
            split2(x0, x1, hi4.x, lo4.x);
            x0 = valid ? __ldcs(xb + 12800) : 0.f;
            x1 = valid ? __ldcs(xb + 19200) : 0.f;
            split2(x0, x1, hi4.y, lo4.y);
            x0 = valid ? __ldcs(xb + 25600) : 0.f;
            x1 = valid ? __ldcs(xb + 32000) : 0.f;
            split2(x0, x1, hi4.z, lo4.z);
            x0 = valid ? __ldcs(xb + 38400) : 0.f;
            x1 = valid ? __ldcs(xb + 44800) : 0.f;
            split2(x0, x1, hi4.w, lo4.w);
            const int i4 = lane * 16 + (b ^ f);
            Xhi4[i4] = hi4;
            Xlo4[i4] = lo4;
        }
    }
    __syncthreads();

    const int row0 = 16 * mh;
    const uint32_t XhiA = smem_u32(Xhi);
    const uint32_t XloA = XhiA + 8192;

    // A-frag LDSM address components (rows row0..row0+15)
    const int rowA = row0 + (lane & 7) + 8 * ((lane >> 3) & 1);
    const uint32_t AoffRow = (uint32_t)rowA * 256;
    const int fA = rowA & 7;
    const int kbA = (lane >> 4) & 1;

    // ---- G = X*M (+u), 3-pass fp16 split, merged acc[16] ----
    float acc[16][4];
#pragma unroll
    for (int nt = 0; nt < 16; nt++)
#pragma unroll
        for (int q = 0; q < 4; q++) acc[nt][q] = 0.f;
#pragma unroll 1
    for (int pass = 0; pass < 3; pass++) {
        const uint32_t Abase = ((pass == 2) ? XloA : XhiA) + AoffRow;
        const uint4* Bp = (const uint4*)g_Wf + ((pass == 1) ? 2048 : 0) + lane;
#pragma unroll
        for (int ks = 0; ks < 8; ks++) {
            uint32_t a[4];
            LDSM_X4(a[0], a[1], a[2], a[3],
                    Abase + (uint32_t)((((2 * ks + kbA) ^ fA)) << 4));
#pragma unroll
            for (int nt2 = 0; nt2 < 8; nt2++) {
                const uint4 b = __ldg(Bp + (ks * 8 + nt2) * 32);
                MMA_F16(acc[2 * nt2], a, b.x, b.y);
                MMA_F16(acc[2 * nt2 + 1], a, b.z, b.w);
            }
        }
    }

    // ---- +u, convert G into A-fragments (acc layout == A-frag layout) ----
    uint32_t GhA[8][4], GlA[8][4];
#pragma unroll
    for (int kk = 0; kk < 8; kk++) {
        float2 ua = *(const float2*)(g_u + 16 * kk + 2 * tc);
        float2 ub = *(const float2*)(g_u + 16 * kk + 8 + 2 * tc);
        float v00 = acc[2 * kk][0] + ua.x, v01 = acc[2 * kk][1] + ua.y;
        float v10 = acc[2 * kk][2] + ua.x, v11 = acc[2 * kk][3] + ua.y;
        float v20 = acc[2 * kk + 1][0] + ub.x, v21 = acc[2 * kk + 1][1] + ub.y;
        float v30 = acc[2 * kk + 1][2] + ub.x, v31 = acc[2 * kk + 1][3] + ub.y;
        unsigned short h00 = f2h(v00), h01 = f2h(v01), h10 = f2h(v10), h11 = f2h(v11);
        unsigned short h20 = f2h(v20), h21 = f2h(v21), h30 = f2h(v30), h31 = f2h(v31);
        GhA[kk][0] = (uint32_t)h00 | ((uint32_t)h01 << 16);
        GhA[kk][1] = (uint32_t)h10 | ((uint32_t)h11 << 16);
        GhA[kk][2] = (uint32_t)h20 | ((uint32_t)h21 << 16);
        GhA[kk][3] = (uint32_t)h30 | ((uint32_t)h31 << 16);
        GlA[kk][0] = packh(v00 - h2f(h00), v01 - h2f(h01));
        GlA[kk][1] = packh(v10 - h2f(h10), v11 - h2f(h11));
        GlA[kk][2] = packh(v20 - h2f(h20), v21 - h2f(h21));
        GlA[kk][3] = packh(v30 - h2f(h30), v31 - h2f(h31));
    }

    // ---- S = G * X^T (3-pass), B-frags via LDSM from X images ----
    const int rowS = (lane & 7) + 8 * ((lane >> 4) & 1);
    const uint32_t SoffRow1 = (uint32_t)rowS * 256;
    const uint32_t SoffRow2 = SoffRow1 + 16 * 256;
    const int fS = lane & 7;
    const int kbS = (lane >> 3) & 1;

    float S[4][4];
#pragma unroll
    for (int nt = 0; nt < 4; nt++)
#pragma unroll
        for (int q = 0; q < 4; q++) S[nt][q] = 0.f;
#pragma unroll 1
    for (int pass = 0; pass < 3; pass++) {
        const uint32_t(*Aa)[4] = (pass == 2) ? GlA : GhA;
        const uint32_t Bbase = (pass == 1) ? XloA : XhiA;
#pragma unroll
        for (int ks = 0; ks < 8; ks++) {
            const uint32_t off = (uint32_t)(((2 * ks + kbS) ^ fS) << 4);
            uint32_t b0, b1, b2, b3, c0, c1, c2, c3;
            LDSM_X4(b0, b1, b2, b3, Bbase + SoffRow1 + off);
            LDSM_X4(c0, c1, c2, c3, Bbase + SoffRow2 + off);
            MMA_F16(S[0], Aa[ks], b0, b1);
            MMA_F16(S[1], Aa[ks], b2, b3);
            MMA_F16(S[2], Aa[ks], c0, c1);
            MMA_F16(S[3], Aa[ks], c2, c3);
        }
    }

    // ---- bias + mask + softmax (rows live in 4-lane groups) ----
    {
        const int v0 = row0 + g;
        const int v1c = (v0 + 8 < 25) ? v0 + 8 : 24;  // index clamp only
#pragma unroll
        for (int nt = 0; nt < 4; nt++) {
            const int w0 = 8 * nt + 2 * tc, w1 = w0 + 1;
            if (w0 < 25) {
                S[nt][0] += g_bias[v0 * 26 + w0];
                S[nt][2] += g_bias[v1c * 26 + w0];
            } else {
                S[nt][0] = -1e30f;
                S[nt][2] = -1e30f;
            }
            if (w1 < 25) {
                S[nt][1] += g_bias[v0 * 26 + w1];
                S[nt][3] += g_bias[v1c * 26 + w1];
            } else {
                S[nt][1] = -1e30f;
                S[nt][3] = -1e30f;
            }
        }
    }
#pragma unroll
    for (int h = 0; h < 2; h++) {
        float mx = -1e30f;
#pragma unroll
        for (int nt = 0; nt < 4; nt++)
            mx = fmaxf(mx, fmaxf(S[nt][2 * h], S[nt][2 * h + 1]));
        mx = fmaxf(mx, __shfl_xor_sync(0xffffffffu, mx, 1));
        mx = fmaxf(mx, __shfl_xor_sync(0xffffffffu, mx, 2));
        float sum = 0.f;
#pragma unroll
        for (int nt = 0; nt < 4; nt++) {
            float e0 = __expf(S[nt][2 * h] - mx);
            float e1 = __expf(S[nt][2 * h + 1] - mx);
            S[nt][2 * h] = e0;
            S[nt][2 * h + 1] = e1;
            sum += e0 + e1;
        }
        sum += __shfl_xor_sync(0xffffffffu, sum, 1);
        sum += __shfl_xor_sync(0xffffffffu, sum, 2);
        float inv = __fdividef(1.f, sum);
#pragma unroll
        for (int nt = 0; nt < 4; nt++) {
            S[nt][2 * h] *= inv;
            S[nt][2 * h + 1] *= inv;
        }
    }

    // ---- P -> fp16 A-fragments (in-register) ----
    uint32_t PA[2][4];
#pragma unroll
    for (int ks = 0; ks < 2; ks++) {
        PA[ks][0] = packh(S[2 * ks][0], S[2 * ks][1]);
        PA[ks][1] = packh(S[2 * ks][2], S[2 * ks][3]);
        PA[ks][2] = packh(S[2 * ks + 1][0], S[2 * ks + 1][1]);
        PA[ks][3] = packh(S[2 * ks + 1][2], S[2 * ks + 1][3]);
    }

    // ---- V = X * wv^T, single-pass fp16 (A via LDSM from Xhi, B uint4 via L1) ----
    float accV[16][4];
#pragma unroll
    for (int nt = 0; nt < 16; nt++)
#pragma unroll
        for (int q = 0; q < 4; q++) accV[nt][q] = 0.f;
    {
        const uint32_t Abase = XhiA + AoffRow;
        const uint4* Bp = (const uint4*)g_Wf + 4096 + lane;
#pragma unroll
        for (int ks = 0; ks < 8; ks++) {
            uint32_t a[4];
            LDSM_X4(a[0], a[1], a[2], a[3],
                    Abase + (uint32_t)((((2 * ks + kbA) ^ fA)) << 4));
#pragma unroll
            for (int nt2 = 0; nt2 < 8; nt2++) {
                const uint4 b = __ldg(Bp + (ks * 8 + nt2) * 32);
                MMA_F16(accV[2 * nt2], a, b.x, b.y);
                MMA_F16(accV[2 * nt2 + 1], a, b.z, b.w);
            }
        }
    }
    __syncthreads();  // all warps done reading X images

    // ---- Vso overlay: V^T fp16 [o][w], fp16 row stride 40 (u32 stride 20) ----
    unsigned short* Vso = (unsigned short*)Xhi;  // 2560 u32 < 4096 (tile region)
#pragma unroll
    for (int nt = 0; nt < 16; nt++) {
        const int r0 = row0 + g, o0 = 8 * nt + 2 * tc;
        Vso[o0 * 40 + r0] = f2h(accV[nt][0]);
        Vso[(o0 + 1) * 40 + r0] = f2h(accV[nt][1]);
        Vso[o0 * 40 + r0 + 8] = f2h(accV[nt][2]);
        Vso[(o0 + 1) * 40 + r0 + 8] = f2h(accV[nt][3]);
    }
    __syncthreads();

    // ---- PV: out[v][o] = P*V via MMA (k = w padded to 32; pads exact zeros) ----
    float accO[16][4];
#pragma unroll
    for (int nt = 0; nt < 16; nt++) {
        float2 bb = *(const float2*)(bv + 8 * nt + 2 * tc);
        accO[nt][0] = bb.x;
        accO[nt][1] = bb.y;
        accO[nt][2] = bb.x;
        accO[nt][3] = bb.y;
    }
    {
        const uint32_t* VsoU = (const uint32_t*)Vso;
#pragma unroll
        for (int ks = 0; ks < 2; ks++) {
#pragma unroll
            for (int nt = 0; nt < 16; nt++) {
                const int orow = (8 * nt + g) * 20;
                uint32_t b0 = VsoU[orow + 8 * ks + tc];
                uint32_t b1 = VsoU[orow + 8 * ks + 4 + tc];
                MMA_F16(accO[nt], PA[ks], b0, b1);
            }
        }
    }
    __syncthreads();  // PV reads of Vso done before overwrite

    // ---- stage outs[o][v] (overwrite tile region), then coalesced store ----
    float* outs = (float*)Xhi;  // 128*26 floats = 3328 u32 < 4096
    {
        const int v0 = row0 + g;
        const int v1 = v0 + 8;
#pragma unroll
        for (int nt = 0; nt < 16; nt++) {
            const int o0 = 8 * nt + 2 * tc;
            outs[o0 * 26 + v0] = accO[nt][0];
            outs[(o0 + 1) * 26 + v0] = accO[nt][1];
            if (v1 < 25) {
                outs[o0 * 26 + v1] = accO[nt][2];
                outs[(o0 + 1) * 26 + v1] = accO[nt][3];
            }
        }
    }
    __syncthreads();

    const long obase = (long)n * 819200 + (long)t * 25;
    {
        int idx = lane + 32 * mh;
        int oo = idx / 25;
        int v = idx - oo * 25;
#pragma unroll 1
        for (int i = 0; i < 50; i++) {
            __stcs(&out[obase + (long)oo * 6400 + v], outs[oo * 26 + v]);
            oo += 2;
            v += 14;
            if (v >= 25) {
                v -= 25;
                oo += 1;
            }
        }
    }
}

extern "C" void kernel_launch(void* const* d_in, const int* in_sizes, int n_in,
                              void* d_out, int out_size) {
    (void)in_sizes; (void)n_in; (void)out_size;
    const float* x = (const float*)d_in[0];
    const float* wq = (const float*)d_in[1];
    const float* bq = (const float*)d_in[2];
    const float* wk = (const float*)d_in[3];
    // d_in[4] = bk: softmax-invariant (row-constant), unused
    const float* wv = (const float*)d_in[5];
    const float* bv = (const float*)d_in[6];
    const float* be = (const float*)d_in[7];
    const int* hop = (const int*)d_in[8];

    cudaFuncSetAttribute(fused_kernel, cudaFuncAttributeMaxDynamicSharedMemorySize,
                         65536);

    precompute_kernel<<<130, 128>>>(wq, bq, wk, wv, be, hop);
    fused_kernel<<<NT_TOTAL / 4, 256, 65536>>>(x, bv, (float*)d_out);
}

// round 15
// speedup vs baseline: 3.3104x; 1.0523x over previous
#include <cuda_runtime.h>
#include <cstdint>

// PhysicsAttention: N=64, C=128, T=256, V=25, O=128
// Round 15: n-split warp pairs. Each warp: all 32 rows (m32) x its n-half.
// Weight B-fragments read once per tile (was twice). S = k-split partial + smem
// exchange; P broadcast via smem + LDSM. Named pair-barriers. 2 CTAs/SM.

#define NT_TOTAL 16384

__device__ uint32_t g_Wf[24576];  // fp16 frag images: Mhi | Mlo | Vf16 (8192 u32 each)
__device__ float g_u[128];
__device__ float g_bias[25 * 26];

// ---------------- helpers ----------------
__device__ __forceinline__ unsigned short f2h(float f) {
    unsigned short u;
    asm("cvt.rn.f16.f32 %0, %1;" : "=h"(u) : "f"(f));
    return u;
}
__device__ __forceinline__ float h2f(unsigned short u) {
    float f;
    asm("cvt.f32.f16 %0, %1;" : "=f"(f) : "h"(u));
    return f;
}
__device__ __forceinline__ uint32_t packh(float a, float b) {
    return (uint32_t)f2h(a) | ((uint32_t)f2h(b) << 16);
}
__device__ __forceinline__ void split2(float x0, float x1, uint32_t& hi, uint32_t& lo) {
    unsigned short h0 = f2h(x0), h1 = f2h(x1);
    hi = (uint32_t)h0 | ((uint32_t)h1 << 16);
    lo = packh(x0 - h2f(h0), x1 - h2f(h1));
}
__device__ __forceinline__ uint32_t smem_u32(const void* p) {
    uint32_t a;
    asm("{ .reg .u64 t; cvta.to.shared.u64 t, %1; cvt.u32.u64 %0, t; }" : "=r"(a) : "l"(p));
    return a;
}

#define MMA_F16(d, a, b0v, b1v)                                                   \
    asm("mma.sync.aligned.m16n8k16.row.col.f32.f16.f16.f32 "                      \
        "{%0,%1,%2,%3},{%4,%5,%6,%7},{%8,%9},{%0,%1,%2,%3};"                      \
        : "+f"((d)[0]), "+f"((d)[1]), "+f"((d)[2]), "+f"((d)[3])                  \
        : "r"((a)[0]), "r"((a)[1]), "r"((a)[2]), "r"((a)[3]), "r"(b0v), "r"(b1v))

#define LDSM_X4(r0, r1, r2, r3, addr)                                             \
    asm volatile("ldmatrix.sync.aligned.m8n8.x4.shared.b16 {%0,%1,%2,%3}, [%4];"  \
                 : "=r"(r0), "=r"(r1), "=r"(r2), "=r"(r3) : "r"(addr))

#define PAIR_BAR() asm volatile("bar.sync %0, 64;" :: "r"(tp + 1) : "memory")

// ---------------- precompute: frag-ordered fp16 weight images, u, bias (proven R14) ----
__global__ void precompute_kernel(const float* __restrict__ wq,
                                  const float* __restrict__ bq,
                                  const float* __restrict__ wk,
                                  const float* __restrict__ wv,
                                  const float* __restrict__ bias_emb,
                                  const int* __restrict__ hop) {
    const float inv = 0.088388347648318447f;  // 1/sqrt(128)
    int b = blockIdx.x, k = threadIdx.x;
    if (b < 128) {
        const int n = b;
        float m = 0.f;
#pragma unroll 8
        for (int o = 0; o < 128; o++) m += wq[o * 128 + k] * wk[o * 128 + n];
        m *= inv;
        float wvv = wv[n * 128 + k];
        const int nt = n >> 3, j = n & 7, i = k & 15, ks = k >> 4;
        const int lane = j * 4 + ((i & 7) >> 1);
        const int reg = i >> 3;
        const int half = i & 1;
        const int u32idx = (((ks * 8 + (nt >> 1)) * 32 + lane) << 2) + ((nt & 1) << 1) + reg;
        unsigned short* B16 = (unsigned short*)g_Wf;
        unsigned short mh = f2h(m);
        B16[(0 * 8192 + u32idx) * 2 + half] = mh;                // Mhi
        B16[(1 * 8192 + u32idx) * 2 + half] = f2h(m - h2f(mh));  // Mlo
        B16[(2 * 8192 + u32idx) * 2 + half] = f2h(wvv);          // Vf16
    } else if (b == 128) {
        float uu = 0.f;
#pragma unroll 8
        for (int o = 0; o < 128; o++) uu += bq[o] * wk[o * 128 + k];
        g_u[k] = uu * inv;
    } else {
        for (int i = k; i < 625; i += 128) {
            int v = i / 25, w = i - v * 25;
            g_bias[v * 26 + w] = bias_emb[hop[i]];
        }
    }
}

// ---------------- fused kernel: 8 warps/CTA, n-split warp-pair per tile ----------------
// per-tile smem: Xhi 8KB | Xlo 8KB | Ex 5KB = 21504 B; x4 tiles = 86016 B -> 2 CTAs/SM
extern __shared__ uint32_t sm[];

__global__ __launch_bounds__(256, 2) void fused_kernel(const float* __restrict__ x,
                                                       const float* __restrict__ bv,
                                                       float* __restrict__ out) {
    const int tid = threadIdx.x;
    const int lane = tid & 31;
    const int w = tid >> 5;
    const int nh = w & 1;   // n-half within the tile
    const int tp = w >> 1;  // tile slot 0..3
    const int g = lane >> 2, tc = lane & 3;

    uint32_t* Xhi = sm + tp * 5376;  // 2048 u32
    uint32_t* Xlo = Xhi + 2048;      // 2048 u32
    uint32_t* Ex = Xhi + 4096;       // 1280 u32 (5KB): Spar then Pbuf

    const int tile = blockIdx.x * 4 + tp;
    const int n = tile >> 8;
    const int t = tile & 255;
    const long xbase = (long)n * 819200 + (long)t * 25;

    // ---- x tile -> fp16 hi/lo images; pair splits block range (lane = row v) ----
    // X-image: [row][16B block b], swizzled: uint4 idx = row*16 + (b ^ (row&7)).
    {
        const bool valid = lane < 25;
        const float* xr = x + xbase + lane;
        uint4* Xhi4 = (uint4*)Xhi;
        uint4* Xlo4 = (uint4*)Xlo;
        const int f = lane & 7;
#pragma unroll 2
        for (int j = 0; j < 8; j++) {
            const int b = nh * 8 + j;  // 16B block = 4 u32 = 8 channels
            const float* xb = xr + (long)b * 51200;
            uint4 hi4, lo4;
            float x0, x1;
            x0 = valid ? __ldcs(xb + 0) : 0.f;
            x1 = valid ? __ldcs(xb + 6400) : 0.f;
            split2(x0, x1, hi4.x, lo4.x);
            x0 = valid ? __ldcs(xb + 12800) : 0.f;
            x1 = valid ? __ldcs(xb + 19200) : 0.f;
            split2(x0, x1, hi4.y, lo4.y);
            x0 = valid ? __ldcs(xb + 25600) : 0.f;
            x1 = valid ? __ldcs(xb + 32000) : 0.f;
            split2(x0, x1, hi4.z, lo4.z);
            x0 = valid ? __ldcs(xb + 38400) : 0.f;
            x1 = valid ? __ldcs(xb + 44800) : 0.f;
            split2(x0, x1, hi4.w, lo4.w);
            const int i4 = lane * 16 + (b ^ f);
            Xhi4[i4] = hi4;
            Xlo4[i4] = lo4;
        }
    }
    __syncthreads();

    const uint32_t XhiA = smem_u32(Xhi);
    const uint32_t XloA = XhiA + 8192;
    const uint32_t ExA = XhiA + 16384;

    // A-frag LDSM components (both m-tiles)
    const int rA = (lane & 7) + 8 * ((lane >> 3) & 1);
    const uint32_t Aoff0 = (uint32_t)rA * 256;      // rows 0-15
    const uint32_t Aoff1 = Aoff0 + 16 * 256;        // rows 16-31
    const int fA = rA & 7;
    const int kbA = (lane >> 4) & 1;

    // ---- G = X*M (+u), 3-pass, m32 x n64 (this warp's n-half) ----
    float acc[2][8][4];
#pragma unroll
    for (int mt = 0; mt < 2; mt++)
#pragma unroll
        for (int nt = 0; nt < 8; nt++)
#pragma unroll
            for (int q = 0; q < 4; q++) acc[mt][nt][q] = 0.f;
#pragma unroll 1
    for (int pass = 0; pass < 3; pass++) {
        const uint32_t Abase = (pass == 2) ? XloA : XhiA;
        const uint4* Bp = (const uint4*)g_Wf + ((pass == 1) ? 2048 : 0) + lane;
#pragma unroll
        for (int ks = 0; ks < 8; ks++) {
            const uint32_t koff = (uint32_t)(((2 * ks + kbA) ^ fA) << 4);
            uint32_t a0[4], a1[4];
            LDSM_X4(a0[0], a0[1], a0[2], a0[3], Abase + Aoff0 + koff);
            LDSM_X4(a1[0], a1[1], a1[2], a1[3], Abase + Aoff1 + koff);
#pragma unroll
            for (int nt2 = 0; nt2 < 4; nt2++) {
                const uint4 b = __ldg(Bp + (ks * 8 + 4 * nh + nt2) * 32);
                MMA_F16(acc[0][2 * nt2], a0, b.x, b.y);
                MMA_F16(acc[0][2 * nt2 + 1], a0, b.z, b.w);
                MMA_F16(acc[1][2 * nt2], a1, b.x, b.y);
                MMA_F16(acc[1][2 * nt2 + 1], a1, b.z, b.w);
            }
        }
    }

    // ---- +u, convert G into A-fragments for the S GEMM (k-chunks 4nh..4nh+3) ----
    uint32_t GhA[2][4][4], GlA[2][4][4];
#pragma unroll
    for (int kkl = 0; kkl < 4; kkl++) {
        const int kk = 4 * nh + kkl;
        float2 ua = *(const float2*)(g_u + 16 * kk + 2 * tc);
        float2 ub = *(const float2*)(g_u + 16 * kk + 8 + 2 * tc);
#pragma unroll
        for (int mt = 0; mt < 2; mt++) {
            float v00 = acc[mt][2 * kkl][0] + ua.x, v01 = acc[mt][2 * kkl][1] + ua.y;
            float v10 = acc[mt][2 * kkl][2] + ua.x, v11 = acc[mt][2 * kkl][3] + ua.y;
            float v20 = acc[mt][2 * kkl + 1][0] + ub.x, v21 = acc[mt][2 * kkl + 1][1] + ub.y;
            float v30 = acc[mt][2 * kkl + 1][2] + ub.x, v31 = acc[mt][2 * kkl + 1][3] + ub.y;
            unsigned short h00 = f2h(v00), h01 = f2h(v01), h10 = f2h(v10), h11 = f2h(v11);
            unsigned short h20 = f2h(v20), h21 = f2h(v21), h30 = f2h(v30), h31 = f2h(v31);
            GhA[mt][kkl][0] = (uint32_t)h00 | ((uint32_t)h01 << 16);
            GhA[mt][kkl][1] = (uint32_t)h10 | ((uint32_t)h11 << 16);
            GhA[mt][kkl][2] = (uint32_t)h20 | ((uint32_t)h21 << 16);
            GhA[mt][kkl][3] = (uint32_t)h30 | ((uint32_t)h31 << 16);
            GlA[mt][kkl][0] = packh(v00 - h2f(h00), v01 - h2f(h01));
            GlA[mt][kkl][1] = packh(v10 - h2f(h10), v11 - h2f(h11));
            GlA[mt][kkl][2] = packh(v20 - h2f(h20), v21 - h2f(h21));
            GlA[mt][kkl][3] = packh(v30 - h2f(h30), v31 - h2f(h31));
        }
    }

    // ---- S partial = G(:, k-half) * X(:, k-half)^T, m32 x n32 ----
    const int rS = (lane & 7) + 8 * ((lane >> 4) & 1);
    const uint32_t SoffRow1 = (uint32_t)rS * 256;
    const uint32_t SoffRow2 = SoffRow1 + 16 * 256;
    const int fS = lane & 7;
    const int kbS = (lane >> 3) & 1;

    float S[2][4][4];
#pragma unroll
    for (int mt = 0; mt < 2; mt++)
#pragma unroll
        for (int nt = 0; nt < 4; nt++)
#pragma unroll
            for (int q = 0; q < 4; q++) S[mt][nt][q] = 0.f;
#pragma unroll 1
    for (int pass = 0; pass < 3; pass++) {
        const uint32_t(*Aa)[4][4] = (pass == 2) ? GlA : GhA;
        const uint32_t Bbase = (pass == 1) ? XloA : XhiA;
#pragma unroll
        for (int ksl = 0; ksl < 4; ksl++) {
            const int kg = 4 * nh + ksl;
            const uint32_t off = (uint32_t)(((2 * kg + kbS) ^ fS) << 4);
            uint32_t b0, b1, b2, b3, c0, c1, c2, c3;
            LDSM_X4(b0, b1, b2, b3, Bbase + SoffRow1 + off);
            LDSM_X4(c0, c1, c2, c3, Bbase + SoffRow2 + off);
            MMA_F16(S[0][0], Aa[0][ksl], b0, b1);
            MMA_F16(S[0][1], Aa[0][ksl], b2, b3);
            MMA_F16(S[0][2], Aa[0][ksl], c0, c1);
            MMA_F16(S[0][3], Aa[0][ksl], c2, c3);
            MMA_F16(S[1][0], Aa[1][ksl], b0, b1);
            MMA_F16(S[1][1], Aa[1][ksl], b2, b3);
            MMA_F16(S[1][2], Aa[1][ksl], c0, c1);
            MMA_F16(S[1][3], Aa[1][ksl], c2, c3);
        }
    }

    // ---- exchange: store partial for the OTHER m-half; keep own ----
    {
        float* Sp = (float*)Ex + nh * 544;  // [16 rows][stride 34]
        const int mto = 1 - nh;
#pragma unroll
        for (int nt = 0; nt < 4; nt++) {
            const int w0 = 8 * nt + 2 * tc;
            *(float2*)&Sp[g * 34 + w0] = make_float2(S[mto][nt][0], S[mto][nt][1]);
            *(float2*)&Sp[(g + 8) * 34 + w0] = make_float2(S[mto][nt][2], S[mto][nt][3]);
        }
    }
    PAIR_BAR();
    {
        const float* Sq = (float*)Ex + (1 - nh) * 544;
#pragma unroll
        for (int nt = 0; nt < 4; nt++) {
            const int w0 = 8 * nt + 2 * tc;
            float2 p0 = *(const float2*)&Sq[g * 34 + w0];
            float2 p1 = *(const float2*)&Sq[(g + 8) * 34 + w0];
            S[nh][nt][0] += p0.x;
            S[nh][nt][1] += p0.y;
            S[nh][nt][2] += p1.x;
            S[nh][nt][3] += p1.y;
        }
    }

    // ---- bias + mask + softmax on own rows (v = 16nh + g, +8) ----
    float Sv[4][4];
#pragma unroll
    for (int nt = 0; nt < 4; nt++)
#pragma unroll
        for (int q = 0; q < 4; q++) Sv[nt][q] = S[nh][nt][q];
    {
        const int v0 = 16 * nh + g;
        const int v1c = (v0 + 8 < 25) ? v0 + 8 : 24;  // index clamp only
#pragma unroll
        for (int nt = 0; nt < 4; nt++) {
            const int w0 = 8 * nt + 2 * tc, w1 = w0 + 1;
            if (w0 < 25) {
                Sv[nt][0] += g_bias[v0 * 26 + w0];
                Sv[nt][2] += g_bias[v1c * 26 + w0];
            } else {
                Sv[nt][0] = -1e30f;
                Sv[nt][2] = -1e30f;
            }
            if (w1 < 25) {
                Sv[nt][1] += g_bias[v0 * 26 + w1];
                Sv[nt][3] += g_bias[v1c * 26 + w1];
            } else {
                Sv[nt][1] = -1e30f;
                Sv[nt][3] = -1e30f;
            }
        }
    }
#pragma unroll
    for (int h = 0; h < 2; h++) {
        float mx = -1e30f;
#pragma unroll
        for (int nt = 0; nt < 4; nt++)
            mx = fmaxf(mx, fmaxf(Sv[nt][2 * h], Sv[nt][2 * h + 1]));
        mx = fmaxf(mx, __shfl_xor_sync(0xffffffffu, mx, 1));
        mx = fmaxf(mx, __shfl_xor_sync(0xffffffffu, mx, 2));
        float sum = 0.f;
#pragma unroll
        for (int nt = 0; nt < 4; nt++) {
            float e0 = __expf(Sv[nt][2 * h] - mx);
            float e1 = __expf(Sv[nt][2 * h + 1] - mx);
            Sv[nt][2 * h] = e0;
            Sv[nt][2 * h + 1] = e1;
            sum += e0 + e1;
        }
        sum += __shfl_xor_sync(0xffffffffu, sum, 1);
        sum += __shfl_xor_sync(0xffffffffu, sum, 2);
        float inv = __fdividef(1.f, sum);
#pragma unroll
        for (int nt = 0; nt < 4; nt++) {
            Sv[nt][2 * h] *= inv;
            Sv[nt][2 * h + 1] *= inv;
        }
    }
    PAIR_BAR();  // Spar reads done; Ex reusable as Pbuf

    // ---- P -> Pbuf fp16 [32 rows v][stride 40 halfs] ----
    {
        uint32_t* Pb = Ex;
#pragma unroll
        for (int nt = 0; nt < 4; nt++) {
            Pb[(16 * nh + g) * 20 + 4 * nt + tc] = packh(Sv[nt][0], Sv[nt][1]);
            Pb[(16 * nh + g + 8) * 20 + 4 * nt + tc] = packh(Sv[nt][2], Sv[nt][3]);
        }
    }

    // ---- V = X * wv^T, single-pass fp16, m32 x n64 (this warp's o-half) ----
    float accV[2][8][4];
#pragma unroll
    for (int mt = 0; mt < 2; mt++)
#pragma unroll
        for (int nt = 0; nt < 8; nt++)
#pragma unroll
            for (int q = 0; q < 4; q++) accV[mt][nt][q] = 0.f;
    {
        const uint4* Bp = (const uint4*)g_Wf + 4096 + lane;
#pragma unroll
        for (int ks = 0; ks < 8; ks++) {
            const uint32_t koff = (uint32_t)(((2 * ks + kbA) ^ fA) << 4);
            uint32_t a0[4], a1[4];
            LDSM_X4(a0[0], a0[1], a0[2], a0[3], XhiA + Aoff0 + koff);
            LDSM_X4(a1[0], a1[1], a1[2], a1[3], XhiA + Aoff1 + koff);
#pragma unroll
            for (int nt2 = 0; nt2 < 4; nt2++) {
                const uint4 b = __ldg(Bp + (ks * 8 + 4 * nh + nt2) * 32);
                MMA_F16(accV[0][2 * nt2], a0, b.x, b.y);
                MMA_F16(accV[0][2 * nt2 + 1], a0, b.z, b.w);
                MMA_F16(accV[1][2 * nt2], a1, b.x, b.y);
                MMA_F16(accV[1][2 * nt2 + 1], a1, b.z, b.w);
            }
        }
    }
    PAIR_BAR();  // Pbuf ready; pair done reading X images

    // ---- PA: LDSM P A-fragments for full m32 ----
    uint32_t PA[2][2][4];
    {
        const int rowP = (lane & 7) + 8 * ((lane >> 3) & 1);
        const uint32_t blkk = (uint32_t)((lane >> 4) & 1);
#pragma unroll
        for (int mt = 0; mt < 2; mt++)
#pragma unroll
            for (int ks2 = 0; ks2 < 2; ks2++) {
                LDSM_X4(PA[mt][ks2][0], PA[mt][ks2][1], PA[mt][ks2][2], PA[mt][ks2][3],
                        ExA + (uint32_t)(16 * mt + rowP) * 80 + (2 * ks2 + blkk) * 16);
            }
    }

    // ---- Vso overlay: V^T fp16 [o][w], stride 40 halfs (this warp writes its o-half) ----
    unsigned short* Vso = (unsigned short*)Xhi;  // 10240 B over Xhi+Xlo (both dead)
#pragma unroll
    for (int mt = 0; mt < 2; mt++)
#pragma unroll
        for (int nt = 0; nt < 8; nt++) {
            const int o0 = 64 * nh + 8 * nt + 2 * tc, r0 = 16 * mt + g;
            Vso[o0 * 40 + r0] = f2h(accV[mt][nt][0]);
            Vso[(o0 + 1) * 40 + r0] = f2h(accV[mt][nt][1]);
            Vso[o0 * 40 + r0 + 8] = f2h(accV[mt][nt][2]);
            Vso[(o0 + 1) * 40 + r0 + 8] = f2h(accV[mt][nt][3]);
        }
    PAIR_BAR();

    // ---- PV: out = P*V + bv, m32 x o-half (k = w padded to 32, pads exact zeros) ----
    float accO[2][8][4];
#pragma unroll
    for (int nt = 0; nt < 8; nt++) {
        float2 bb = *(const float2*)(bv + 64 * nh + 8 * nt + 2 * tc);
#pragma unroll
        for (int mt = 0; mt < 2; mt++) {
            accO[mt][nt][0] = bb.x;
            accO[mt][nt][1] = bb.y;
            accO[mt][nt][2] = bb.x;
            accO[mt][nt][3] = bb.y;
        }
    }
    {
        const uint32_t* VsoU = (const uint32_t*)Vso;
#pragma unroll
        for (int ks2 = 0; ks2 < 2; ks2++) {
#pragma unroll
            for (int nt = 0; nt < 8; nt++) {
                const int orow = (64 * nh + 8 * nt + g) * 20;
                uint32_t b0 = VsoU[orow + 8 * ks2 + tc];
                uint32_t b1 = VsoU[orow + 8 * ks2 + 4 + tc];
                MMA_F16(accO[0][nt], PA[0][ks2], b0, b1);
                MMA_F16(accO[1][nt], PA[1][ks2], b0, b1);
            }
        }
    }
    PAIR_BAR();  // Vso reads done before overwrite

    // ---- stage outs[o][v] (overwrite tile region), then coalesced store ----
    float* outs = (float*)Xhi;  // 128*26 floats = 13312 B over Xhi+Xlo
#pragma unroll
    for (int mt = 0; mt < 2; mt++) {
        const int v0 = 16 * mt + g;
        const int v1 = v0 + 8;
#pragma unroll
        for (int nt = 0; nt < 8; nt++) {
            const int o0 = 64 * nh + 8 * nt + 2 * tc;
            outs[o0 * 26 + v0] = accO[mt][nt][0];
            outs[(o0 + 1) * 26 + v0] = accO[mt][nt][1];
            if (v1 < 25) {
                outs[o0 * 26 + v1] = accO[mt][nt][2];
                outs[(o0 + 1) * 26 + v1] = accO[mt][nt][3];
            }
        }
    }
    PAIR_BAR();

    const long obase = (long)n * 819200 + (long)t * 25;
    {
        int idx = lane + 32 * nh;
        int oo = idx / 25;
        int v = idx - oo * 25;
#pragma unroll 1
        for (int i = 0; i < 50; i++) {
            __stcs(&out[obase + (long)oo * 6400 + v], outs[oo * 26 + v]);
            oo += 2;
            v += 14;
            if (v >= 25) {
                v -= 25;
                oo += 1;
            }
        }
    }
}

extern "C" void kernel_launch(void* const* d_in, const int* in_sizes, int n_in,
                              void* d_out, int out_size) {
    (void)in_sizes; (void)n_in; (void)out_size;
    const float* x = (const float*)d_in[0];
    const float* wq = (const float*)d_in[1];
    const float* bq = (const float*)d_in[2];
    const float* wk = (const float*)d_in[3];
    // d_in[4] = bk: softmax-invariant (row-constant), unused
    const float* wv = (const float*)d_in[5];
    const float* bv = (const float*)d_in[6];
    const float* be = (const float*)d_in[7];
    const int* hop = (const int*)d_in[8];

    cudaFuncSetAttribute(fused_kernel, cudaFuncAttributeMaxDynamicSharedMemorySize,
                         86016);

    precompute_kernel<<<130, 128>>>(wq, bq, wk, wv, be, hop);
    fused_kernel<<<NT_TOTAL / 4, 256, 86016>>>(x, bv, (float*)d_out);
}

// round 16
// speedup vs baseline: 4.0032x; 1.2093x over previous
#include <cuda_runtime.h>
#include <cstdint>

// PhysicsAttention: N=64, C=128, T=256, V=25, O=128
// Round 16: R15 + k-fused split passes (shared Bh/A operands read once per k-step:
// G B-LDG 96->64, G A-LDSM 48->32, S B-LDSM 24->16 per warp) + direct-STG epilogue.

#define NT_TOTAL 16384

__device__ uint32_t g_Wf[24576];  // fp16 frag images: Mhi | Mlo | Vf16 (8192 u32 each)
__device__ float g_u[128];
__device__ float g_bias[25 * 26];

// ---------------- helpers ----------------
__device__ __forceinline__ unsigned short f2h(float f) {
    unsigned short u;
    asm("cvt.rn.f16.f32 %0, %1;" : "=h"(u) : "f"(f));
    return u;
}
__device__ __forceinline__ float h2f(unsigned short u) {
    float f;
    asm("cvt.f32.f16 %0, %1;" : "=f"(f) : "h"(u));
    return f;
}
__device__ __forceinline__ uint32_t packh(float a, float b) {
    return (uint32_t)f2h(a) | ((uint32_t)f2h(b) << 16);
}
__device__ __forceinline__ void split2(float x0, float x1, uint32_t& hi, uint32_t& lo) {
    unsigned short h0 = f2h(x0), h1 = f2h(x1);
    hi = (uint32_t)h0 | ((uint32_t)h1 << 16);
    lo = packh(x0 - h2f(h0), x1 - h2f(h1));
}
__device__ __forceinline__ uint32_t smem_u32(const void* p) {
    uint32_t a;
    asm("{ .reg .u64 t; cvta.to.shared.u64 t, %1; cvt.u32.u64 %0, t; }" : "=r"(a) : "l"(p));
    return a;
}

#define MMA_F16(d, a, b0v, b1v)                                                   \
    asm("mma.sync.aligned.m16n8k16.row.col.f32.f16.f16.f32 "                      \
        "{%0,%1,%2,%3},{%4,%5,%6,%7},{%8,%9},{%0,%1,%2,%3};"                      \
        : "+f"((d)[0]), "+f"((d)[1]), "+f"((d)[2]), "+f"((d)[3])                  \
        : "r"((a)[0]), "r"((a)[1]), "r"((a)[2]), "r"((a)[3]), "r"(b0v), "r"(b1v))

#define LDSM_X4(r0, r1, r2, r3, addr)                                             \
    asm volatile("ldmatrix.sync.aligned.m8n8.x4.shared.b16 {%0,%1,%2,%3}, [%4];"  \
                 : "=r"(r0), "=r"(r1), "=r"(r2), "=r"(r3) : "r"(addr))

#define PAIR_BAR() asm volatile("bar.sync %0, 64;" :: "r"(tp + 1) : "memory")

// ---------------- precompute: frag-ordered fp16 weight images, u, bias (proven) ----
__global__ void precompute_kernel(const float* __restrict__ wq,
                                  const float* __restrict__ bq,
                                  const float* __restrict__ wk,
                                  const float* __restrict__ wv,
                                  const float* __restrict__ bias_emb,
                                  const int* __restrict__ hop) {
    const float inv = 0.088388347648318447f;  // 1/sqrt(128)
    int b = blockIdx.x, k = threadIdx.x;
    if (b < 128) {
        const int n = b;
        float m = 0.f;
#pragma unroll 8
        for (int o = 0; o < 128; o++) m += wq[o * 128 + k] * wk[o * 128 + n];
        m *= inv;
        float wvv = wv[n * 128 + k];
        const int nt = n >> 3, j = n & 7, i = k & 15, ks = k >> 4;
        const int lane = j * 4 + ((i & 7) >> 1);
        const int reg = i >> 3;
        const int half = i & 1;
        const int u32idx = (((ks * 8 + (nt >> 1)) * 32 + lane) << 2) + ((nt & 1) << 1) + reg;
        unsigned short* B16 = (unsigned short*)g_Wf;
        unsigned short mh = f2h(m);
        B16[(0 * 8192 + u32idx) * 2 + half] = mh;                // Mhi
        B16[(1 * 8192 + u32idx) * 2 + half] = f2h(m - h2f(mh));  // Mlo
        B16[(2 * 8192 + u32idx) * 2 + half] = f2h(wvv);          // Vf16
    } else if (b == 128) {
        float uu = 0.f;
#pragma unroll 8
        for (int o = 0; o < 128; o++) uu += bq[o] * wk[o * 128 + k];
        g_u[k] = uu * inv;
    } else {
        for (int i = k; i < 625; i += 128) {
            int v = i / 25, w = i - v * 25;
            g_bias[v * 26 + w] = bias_emb[hop[i]];
        }
    }
}

// ---------------- fused kernel: 8 warps/CTA, n-split warp-pair per tile ----------------
// per-tile smem: Xhi 8KB | Xlo 8KB | Ex 5KB = 21504 B; x4 tiles = 86016 B -> 2 CTAs/SM
extern __shared__ uint32_t sm[];

__global__ __launch_bounds__(256, 2) void fused_kernel(const float* __restrict__ x,
                                                       const float* __restrict__ bv,
                                                       float* __restrict__ out) {
    const int tid = threadIdx.x;
    const int lane = tid & 31;
    const int w = tid >> 5;
    const int nh = w & 1;   // n-half within the tile
    const int tp = w >> 1;  // tile slot 0..3
    const int g = lane >> 2, tc = lane & 3;

    uint32_t* Xhi = sm + tp * 5376;  // 2048 u32
    uint32_t* Xlo = Xhi + 2048;      // 2048 u32
    uint32_t* Ex = Xhi + 4096;       // 1280 u32 (5KB): Spar then Pbuf

    const int tile = blockIdx.x * 4 + tp;
    const int n = tile >> 8;
    const int t = tile & 255;
    const long xbase = (long)n * 819200 + (long)t * 25;

    // ---- x tile -> fp16 hi/lo images; pair splits block range (lane = row v) ----
    // X-image: [row][16B block b], swizzled: uint4 idx = row*16 + (b ^ (row&7)).
    {
        const bool valid = lane < 25;
        const float* xr = x + xbase + lane;
        uint4* Xhi4 = (uint4*)Xhi;
        uint4* Xlo4 = (uint4*)Xlo;
        const int f = lane & 7;
#pragma unroll 2
        for (int j = 0; j < 8; j++) {
            const int b = nh * 8 + j;  // 16B block = 4 u32 = 8 channels
            const float* xb = xr + (long)b * 51200;
            uint4 hi4, lo4;
            float x0, x1;
            x0 = valid ? __ldcs(xb + 0) : 0.f;
            x1 = valid ? __ldcs(xb + 6400) : 0.f;
            split2(x0, x1, hi4.x, lo4.x);
            x0 = valid ? __ldcs(xb + 12800) : 0.f;
            x1 = valid ? __ldcs(xb + 19200) : 0.f;
            split2(x0, x1, hi4.y, lo4.y);
            x0 = valid ? __ldcs(xb + 25600) : 0.f;
            x1 = valid ? __ldcs(xb + 32000) : 0.f;
            split2(x0, x1, hi4.z, lo4.z);
            x0 = valid ? __ldcs(xb + 38400) : 0.f;
            x1 = valid ? __ldcs(xb + 44800) : 0.f;
            split2(x0, x1, hi4.w, lo4.w);
            const int i4 = lane * 16 + (b ^ f);
            Xhi4[i4] = hi4;
            Xlo4[i4] = lo4;
        }
    }
    __syncthreads();

    const uint32_t XhiA = smem_u32(Xhi);
    const uint32_t XloA = XhiA + 8192;
    const uint32_t ExA = XhiA + 16384;

    // A-frag LDSM components (both m-tiles)
    const int rA = (lane & 7) + 8 * ((lane >> 3) & 1);
    const uint32_t Aoff0 = (uint32_t)rA * 256;  // rows 0-15
    const uint32_t Aoff1 = Aoff0 + 16 * 256;    // rows 16-31
    const int fA = rA & 7;
    const int kbA = (lane >> 4) & 1;

    // ---- G = X*M (+u), k-fused 3-term split, m32 x n64 (this warp's n-half) ----
    // Per ks: load Ah0,Ah1,Al0,Al1 + Bh,Bl once; issue Ah*Bh, Al*Bh, Ah*Bl.
    float acc[2][8][4];
#pragma unroll
    for (int mt = 0; mt < 2; mt++)
#pragma unroll
        for (int nt = 0; nt < 8; nt++)
#pragma unroll
            for (int q = 0; q < 4; q++) acc[mt][nt][q] = 0.f;
    {
        const uint4* BpH = (const uint4*)g_Wf + lane;
        const uint4* BpL = BpH + 2048;
#pragma unroll
        for (int ks = 0; ks < 8; ks++) {
            const uint32_t koff = (uint32_t)(((2 * ks + kbA) ^ fA) << 4);
            uint32_t ah0[4], ah1[4], al0[4], al1[4];
            LDSM_X4(ah0[0], ah0[1], ah0[2], ah0[3], XhiA + Aoff0 + koff);
            LDSM_X4(ah1[0], ah1[1], ah1[2], ah1[3], XhiA + Aoff1 + koff);
            LDSM_X4(al0[0], al0[1], al0[2], al0[3], XloA + Aoff0 + koff);
            LDSM_X4(al1[0], al1[1], al1[2], al1[3], XloA + Aoff1 + koff);
#pragma unroll
            for (int nt2 = 0; nt2 < 4; nt2++) {
                const int bi = (ks * 8 + 4 * nh + nt2) * 32;
                const uint4 bh = __ldg(BpH + bi);
                MMA_F16(acc[0][2 * nt2], ah0, bh.x, bh.y);
                MMA_F16(acc[0][2 * nt2 + 1], ah0, bh.z, bh.w);
                MMA_F16(acc[1][2 * nt2], ah1, bh.x, bh.y);
                MMA_F16(acc[1][2 * nt2 + 1], ah1, bh.z, bh.w);
                MMA_F16(acc[0][2 * nt2], al0, bh.x, bh.y);
                MMA_F16(acc[0][2 * nt2 + 1], al0, bh.z, bh.w);
                MMA_F16(acc[1][2 * nt2], al1, bh.x, bh.y);
                MMA_F16(acc[1][2 * nt2 + 1], al1, bh.z, bh.w);
                const uint4 bl = __ldg(BpL + bi);
                MMA_F16(acc[0][2 * nt2], ah0, bl.x, bl.y);
                MMA_F16(acc[0][2 * nt2 + 1], ah0, bl.z, bl.w);
                MMA_F16(acc[1][2 * nt2], ah1, bl.x, bl.y);
                MMA_F16(acc[1][2 * nt2 + 1], ah1, bl.z, bl.w);
            }
        }
    }

    // ---- +u, convert G into A-fragments for the S GEMM (k-chunks 4nh..4nh+3) ----
    uint32_t GhA[2][4][4], GlA[2][4][4];
#pragma unroll
    for (int kkl = 0; kkl < 4; kkl++) {
        const int kk = 4 * nh + kkl;
        float2 ua = *(const float2*)(g_u + 16 * kk + 2 * tc);
        float2 ub = *(const float2*)(g_u + 16 * kk + 8 + 2 * tc);
#pragma unroll
        for (int mt = 0; mt < 2; mt++) {
            float v00 = acc[mt][2 * kkl][0] + ua.x, v01 = acc[mt][2 * kkl][1] + ua.y;
            float v10 = acc[mt][2 * kkl][2] + ua.x, v11 = acc[mt][2 * kkl][3] + ua.y;
            float v20 = acc[mt][2 * kkl + 1][0] + ub.x, v21 = acc[mt][2 * kkl + 1][1] + ub.y;
            float v30 = acc[mt][2 * kkl + 1][2] + ub.x, v31 = acc[mt][2 * kkl + 1][3] + ub.y;
            unsigned short h00 = f2h(v00), h01 = f2h(v01), h10 = f2h(v10), h11 = f2h(v11);
            unsigned short h20 = f2h(v20), h21 = f2h(v21), h30 = f2h(v30), h31 = f2h(v31);
            GhA[mt][kkl][0] = (uint32_t)h00 | ((uint32_t)h01 << 16);
            GhA[mt][kkl][1] = (uint32_t)h10 | ((uint32_t)h11 << 16);
            GhA[mt][kkl][2] = (uint32_t)h20 | ((uint32_t)h21 << 16);
            GhA[mt][kkl][3] = (uint32_t)h30 | ((uint32_t)h31 << 16);
            GlA[mt][kkl][0] = packh(v00 - h2f(h00), v01 - h2f(h01));
            GlA[mt][kkl][1] = packh(v10 - h2f(h10), v11 - h2f(h11));
            GlA[mt][kkl][2] = packh(v20 - h2f(h20), v21 - h2f(h21));
            GlA[mt][kkl][3] = packh(v30 - h2f(h30), v31 - h2f(h31));
        }
    }

    // ---- S partial = G(:, k-half) * X(:, k-half)^T, k-fused split, m32 x n32 ----
    const int rS = (lane & 7) + 8 * ((lane >> 4) & 1);
    const uint32_t SoffRow1 = (uint32_t)rS * 256;
    const uint32_t SoffRow2 = SoffRow1 + 16 * 256;
    const int fS = lane & 7;
    const int kbS = (lane >> 3) & 1;

    float S[2][4][4];
#pragma unroll
    for (int mt = 0; mt < 2; mt++)
#pragma unroll
        for (int nt = 0; nt < 4; nt++)
#pragma unroll
            for (int q = 0; q < 4; q++) S[mt][nt][q] = 0.f;
#pragma unroll
    for (int ksl = 0; ksl < 4; ksl++) {
        const int kg = 4 * nh + ksl;
        const uint32_t off = (uint32_t)(((2 * kg + kbS) ^ fS) << 4);
        uint32_t b0, b1, b2, b3, c0, c1, c2, c3;
        // Xh B-frags: used by both Gh and Gl
        LDSM_X4(b0, b1, b2, b3, XhiA + SoffRow1 + off);
        LDSM_X4(c0, c1, c2, c3, XhiA + SoffRow2 + off);
        MMA_F16(S[0][0], GhA[0][ksl], b0, b1);
        MMA_F16(S[0][1], GhA[0][ksl], b2, b3);
        MMA_F16(S[0][2], GhA[0][ksl], c0, c1);
        MMA_F16(S[0][3], GhA[0][ksl], c2, c3);
        MMA_F16(S[1][0], GhA[1][ksl], b0, b1);
        MMA_F16(S[1][1], GhA[1][ksl], b2, b3);
        MMA_F16(S[1][2], GhA[1][ksl], c0, c1);
        MMA_F16(S[1][3], GhA[1][ksl], c2, c3);
        MMA_F16(S[0][0], GlA[0][ksl], b0, b1);
        MMA_F16(S[0][1], GlA[0][ksl], b2, b3);
        MMA_F16(S[0][2], GlA[0][ksl], c0, c1);
        MMA_F16(S[0][3], GlA[0][ksl], c2, c3);
        MMA_F16(S[1][0], GlA[1][ksl], b0, b1);
        MMA_F16(S[1][1], GlA[1][ksl], b2, b3);
        MMA_F16(S[1][2], GlA[1][ksl], c0, c1);
        MMA_F16(S[1][3], GlA[1][ksl], c2, c3);
        // Xl B-frags: Gh only
        LDSM_X4(b0, b1, b2, b3, XloA + SoffRow1 + off);
        LDSM_X4(c0, c1, c2, c3, XloA + SoffRow2 + off);
        MMA_F16(S[0][0], GhA[0][ksl], b0, b1);
        MMA_F16(S[0][1], GhA[0][ksl], b2, b3);
        MMA_F16(S[0][2], GhA[0][ksl], c0, c1);
        MMA_F16(S[0][3], GhA[0][ksl], c2, c3);
        MMA_F16(S[1][0], GhA[1][ksl], b0, b1);
        MMA_F16(S[1][1], GhA[1][ksl], b2, b3);
        MMA_F16(S[1][2], GhA[1][ksl], c0, c1);
        MMA_F16(S[1][3], GhA[1][ksl], c2, c3);
    }

    // ---- exchange: store partial for the OTHER m-half; keep own ----
    {
        float* Sp = (float*)Ex + nh * 544;  // [16 rows][stride 34]
        const int mto = 1 - nh;
#pragma unroll
        for (int nt = 0; nt < 4; nt++) {
            const int w0 = 8 * nt + 2 * tc;
            *(float2*)&Sp[g * 34 + w0] = make_float2(S[mto][nt][0], S[mto][nt][1]);
            *(float2*)&Sp[(g + 8) * 34 + w0] = make_float2(S[mto][nt][2], S[mto][nt][3]);
        }
    }
    PAIR_BAR();
    float Sv[4][4];
    {
        const float* Sq = (float*)Ex + (1 - nh) * 544;
#pragma unroll
        for (int nt = 0; nt < 4; nt++) {
            const int w0 = 8 * nt + 2 * tc;
            float2 p0 = *(const float2*)&Sq[g * 34 + w0];
            float2 p1 = *(const float2*)&Sq[(g + 8) * 34 + w0];
            Sv[nt][0] = S[nh][nt][0] + p0.x;
            Sv[nt][1] = S[nh][nt][1] + p0.y;
            Sv[nt][2] = S[nh][nt][2] + p1.x;
            Sv[nt][3] = S[nh][nt][3] + p1.y;
        }
    }

    // ---- bias + mask + softmax on own rows (v = 16nh + g, +8) ----
    {
        const int v0 = 16 * nh + g;
        const int v1c = (v0 + 8 < 25) ? v0 + 8 : 24;  // index clamp only
#pragma unroll
        for (int nt = 0; nt < 4; nt++) {
            const int w0 = 8 * nt + 2 * tc, w1 = w0 + 1;
            if (w0 < 25) {
                Sv[nt][0] += g_bias[v0 * 26 + w0];
                Sv[nt][2] += g_bias[v1c * 26 + w0];
            } else {
                Sv[nt][0] = -1e30f;
                Sv[nt][2] = -1e30f;
            }
            if (w1 < 25) {
                Sv[nt][1] += g_bias[v0 * 26 + w1];
                Sv[nt][3] += g_bias[v1c * 26 + w1];
            } else {
                Sv[nt][1] = -1e30f;
                Sv[nt][3] = -1e30f;
            }
        }
    }
#pragma unroll
    for (int h = 0; h < 2; h++) {
        float mx = -1e30f;
#pragma unroll
        for (int nt = 0; nt < 4; nt++)
            mx = fmaxf(mx, fmaxf(Sv[nt][2 * h], Sv[nt][2 * h + 1]));
        mx = fmaxf(mx, __shfl_xor_sync(0xffffffffu, mx, 1));
        mx = fmaxf(mx, __shfl_xor_sync(0xffffffffu, mx, 2));
        float sum = 0.f;
#pragma unroll
        for (int nt = 0; nt < 4; nt++) {
            float e0 = __expf(Sv[nt][2 * h] - mx);
            float e1 = __expf(Sv[nt][2 * h + 1] - mx);
            Sv[nt][2 * h] = e0;
            Sv[nt][2 * h + 1] = e1;
            sum += e0 + e1;
        }
        sum += __shfl_xor_sync(0xffffffffu, sum, 1);
        sum += __shfl_xor_sync(0xffffffffu, sum, 2);
        float inv = __fdividef(1.f, sum);
#pragma unroll
        for (int nt = 0; nt < 4; nt++) {
            Sv[nt][2 * h] *= inv;
            Sv[nt][2 * h + 1] *= inv;
        }
    }
    PAIR_BAR();  // Spar reads done; Ex reusable as Pbuf

    // ---- P -> Pbuf fp16 [32 rows v][stride 40 halfs] ----
    {
        uint32_t* Pb = Ex;
#pragma unroll
        for (int nt = 0; nt < 4; nt++) {
            Pb[(16 * nh + g) * 20 + 4 * nt + tc] = packh(Sv[nt][0], Sv[nt][1]);
            Pb[(16 * nh + g + 8) * 20 + 4 * nt + tc] = packh(Sv[nt][2], Sv[nt][3]);
        }
    }

    // ---- V = X * wv^T, single-pass fp16, m32 x n64 (this warp's o-half) ----
    float accV[2][8][4];
#pragma unroll
    for (int mt = 0; mt < 2; mt++)
#pragma unroll
        for (int nt = 0; nt < 8; nt++)
#pragma unroll
            for (int q = 0; q < 4; q++) accV[mt][nt][q] = 0.f;
    {
        const uint4* Bp = (const uint4*)g_Wf + 4096 + lane;
#pragma unroll
        for (int ks = 0; ks < 8; ks++) {
            const uint32_t koff = (uint32_t)(((2 * ks + kbA) ^ fA) << 4);
            uint32_t a0[4], a1[4];
            LDSM_X4(a0[0], a0[1], a0[2], a0[3], XhiA + Aoff0 + koff);
            LDSM_X4(a1[0], a1[1], a1[2], a1[3], XhiA + Aoff1 + koff);
#pragma unroll
            for (int nt2 = 0; nt2 < 4; nt2++) {
                const uint4 b = __ldg(Bp + (ks * 8 + 4 * nh + nt2) * 32);
                MMA_F16(accV[0][2 * nt2], a0, b.x, b.y);
                MMA_F16(accV[0][2 * nt2 + 1], a0, b.z, b.w);
                MMA_F16(accV[1][2 * nt2], a1, b.x, b.y);
                MMA_F16(accV[1][2 * nt2 + 1], a1, b.z, b.w);
            }
        }
    }
    PAIR_BAR();  // Pbuf ready; pair done reading X images

    // ---- PA: LDSM P A-fragments for full m32 ----
    uint32_t PA[2][2][4];
    {
        const int rowP = (lane & 7) + 8 * ((lane >> 3) & 1);
        const uint32_t blkk = (uint32_t)((lane >> 4) & 1);
#pragma unroll
        for (int mt = 0; mt < 2; mt++)
#pragma unroll
            for (int ks2 = 0; ks2 < 2; ks2++) {
                LDSM_X4(PA[mt][ks2][0], PA[mt][ks2][1], PA[mt][ks2][2], PA[mt][ks2][3],
                        ExA + (uint32_t)(16 * mt + rowP) * 80 + (2 * ks2 + blkk) * 16);
            }
    }

    // ---- Vso overlay: V^T fp16 [o][w], stride 40 halfs (this warp writes its o-half) ----
    unsigned short* Vso = (unsigned short*)Xhi;  // 10240 B over Xhi+Xlo (both dead)
#pragma unroll
    for (int mt = 0; mt < 2; mt++)
#pragma unroll
        for (int nt = 0; nt < 8; nt++) {
            const int o0 = 64 * nh + 8 * nt + 2 * tc, r0 = 16 * mt + g;
            Vso[o0 * 40 + r0] = f2h(accV[mt][nt][0]);
            Vso[(o0 + 1) * 40 + r0] = f2h(accV[mt][nt][1]);
            Vso[o0 * 40 + r0 + 8] = f2h(accV[mt][nt][2]);
            Vso[(o0 + 1) * 40 + r0 + 8] = f2h(accV[mt][nt][3]);
        }
    PAIR_BAR();

    // ---- PV: out = P*V + bv, m32 x o-half (k = w padded to 32, pads exact zeros) ----
    float accO[2][8][4];
#pragma unroll
    for (int nt = 0; nt < 8; nt++) {
        float2 bb = *(const float2*)(bv + 64 * nh + 8 * nt + 2 * tc);
#pragma unroll
        for (int mt = 0; mt < 2; mt++) {
            accO[mt][nt][0] = bb.x;
            accO[mt][nt][1] = bb.y;
            accO[mt][nt][2] = bb.x;
            accO[mt][nt][3] = bb.y;
        }
    }
    {
        const uint32_t* VsoU = (const uint32_t*)Vso;
#pragma unroll
        for (int ks2 = 0; ks2 < 2; ks2++) {
#pragma unroll
            for (int nt = 0; nt < 8; nt++) {
                const int orow = (64 * nh + 8 * nt + g) * 20;
                uint32_t b0 = VsoU[orow + 8 * ks2 + tc];
                uint32_t b1 = VsoU[orow + 8 * ks2 + 4 + tc];
                MMA_F16(accO[0][nt], PA[0][ks2], b0, b1);
                MMA_F16(accO[1][nt], PA[1][ks2], b0, b1);
            }
        }
    }

    // ---- direct STG epilogue (no smem staging): 32B-aligned 8-lane v-segments ----
    const long obase = (long)n * 819200 + (long)t * 25;
#pragma unroll
    for (int mt = 0; mt < 2; mt++) {
        const int v0 = 16 * mt + g;
        const int v1 = v0 + 8;
#pragma unroll
        for (int nt = 0; nt < 8; nt++) {
            const int o0 = 64 * nh + 8 * nt + 2 * tc;
            const long p0 = obase + (long)o0 * 6400;
            __stcs(&out[p0 + v0], accO[mt][nt][0]);
            __stcs(&out[p0 + 6400 + v0], accO[mt][nt][1]);
            if (v1 < 25) {
                __stcs(&out[p0 + v1], accO[mt][nt][2]);
                __stcs(&out[p0 + 6400 + v1], accO[mt][nt][3]);
            }
        }
    }
}

extern "C" void kernel_launch(void* const* d_in, const int* in_sizes, int n_in,
                              void* d_out, int out_size) {
    (void)in_sizes; (void)n_in; (void)out_size;
    const float* x = (const float*)d_in[0];
    const float* wq = (const float*)d_in[1];
    const float* bq = (const float*)d_in[2];
    const float* wk = (const float*)d_in[3];
    // d_in[4] = bk: softmax-invariant (row-constant), unused
    const float* wv = (const float*)d_in[5];
    const float* bv = (const float*)d_in[6];
    const float* be = (const float*)d_in[7];
    const int* hop = (const int*)d_in[8];

    cudaFuncSetAttribute(fused_kernel, cudaFuncAttributeMaxDynamicSharedMemorySize,
                         86016);

    precompute_kernel<<<130, 128>>>(wq, bq, wk, wv, be, hop);
    fused_kernel<<<NT_TOTAL / 4, 256, 86016>>>(x, bv, (float*)d_out);
}

// round 17
// speedup vs baseline: 5.5375x; 1.3832x over previous
#include <cuda_runtime.h>
#include <cstdint>

// PhysicsAttention: N=64, C=128, T=256, V=25, O=128
// Round 17: pure single-pass fp16 (no hi/lo split: G=Xh*Mh, S=Gh*Xh^T) -> 320 MMA/warp;
// Xlo image removed (smem 53KB/CTA, weights L1-resident); CTA-wide t-contiguous
// vectorized float4 epilogue. n-split warp-pair structure from R15/16.

#define NT_TOTAL 16384

__device__ uint32_t g_Wf[24576];  // fp16 frag images: Mhi | Mlo(unused) | Vf16 (8192 u32 each)
__device__ float g_u[128];
__device__ float g_bias[25 * 26];

// ---------------- helpers ----------------
__device__ __forceinline__ unsigned short f2h(float f) {
    unsigned short u;
    asm("cvt.rn.f16.f32 %0, %1;" : "=h"(u) : "f"(f));
    return u;
}
__device__ __forceinline__ float h2f(unsigned short u) {
    float f;
    asm("cvt.f32.f16 %0, %1;" : "=f"(f) : "h"(u));
    return f;
}
__device__ __forceinline__ uint32_t packh(float a, float b) {
    return (uint32_t)f2h(a) | ((uint32_t)f2h(b) << 16);
}
__device__ __forceinline__ uint32_t smem_u32(const void* p) {
    uint32_t a;
    asm("{ .reg .u64 t; cvta.to.shared.u64 t, %1; cvt.u32.u64 %0, t; }" : "=r"(a) : "l"(p));
    return a;
}

#define MMA_F16(d, a, b0v, b1v)                                                   \
    asm("mma.sync.aligned.m16n8k16.row.col.f32.f16.f16.f32 "                      \
        "{%0,%1,%2,%3},{%4,%5,%6,%7},{%8,%9},{%0,%1,%2,%3};"                      \
        : "+f"((d)[0]), "+f"((d)[1]), "+f"((d)[2]), "+f"((d)[3])                  \
        : "r"((a)[0]), "r"((a)[1]), "r"((a)[2]), "r"((a)[3]), "r"(b0v), "r"(b1v))

#define LDSM_X4(r0, r1, r2, r3, addr)                                             \
    asm volatile("ldmatrix.sync.aligned.m8n8.x4.shared.b16 {%0,%1,%2,%3}, [%4];"  \
                 : "=r"(r0), "=r"(r1), "=r"(r2), "=r"(r3) : "r"(addr))

#define PAIR_BAR() asm volatile("bar.sync %0, 64;" :: "r"(tp + 1) : "memory")

// ---------------- precompute: frag-ordered fp16 weight images, u, bias (proven) ----
__global__ void precompute_kernel(const float* __restrict__ wq,
                                  const float* __restrict__ bq,
                                  const float* __restrict__ wk,
                                  const float* __restrict__ wv,
                                  const float* __restrict__ bias_emb,
                                  const int* __restrict__ hop) {
    const float inv = 0.088388347648318447f;  // 1/sqrt(128)
    int b = blockIdx.x, k = threadIdx.x;
    if (b < 128) {
        const int n = b;
        float m = 0.f;
#pragma unroll 8
        for (int o = 0; o < 128; o++) m += wq[o * 128 + k] * wk[o * 128 + n];
        m *= inv;
        float wvv = wv[n * 128 + k];
        const int nt = n >> 3, j = n & 7, i = k & 15, ks = k >> 4;
        const int lane = j * 4 + ((i & 7) >> 1);
        const int reg = i >> 3;
        const int half = i & 1;
        const int u32idx = (((ks * 8 + (nt >> 1)) * 32 + lane) << 2) + ((nt & 1) << 1) + reg;
        unsigned short* B16 = (unsigned short*)g_Wf;
        B16[(0 * 8192 + u32idx) * 2 + half] = f2h(m);    // Mhi
        B16[(2 * 8192 + u32idx) * 2 + half] = f2h(wvv);  // Vf16
    } else if (b == 128) {
        float uu = 0.f;
#pragma unroll 8
        for (int o = 0; o < 128; o++) uu += bq[o] * wk[o * 128 + k];
        g_u[k] = uu * inv;
    } else {
        for (int i = k; i < 625; i += 128) {
            int v = i / 25, w = i - v * 25;
            g_bias[v * 26 + w] = bias_emb[hop[i]];
        }
    }
}

// ---------------- fused kernel: 8 warps/CTA, n-split warp-pair per tile ----------------
// per-tile smem: Xhi 8KB | Ex 5KB = 13312 B; x4 tiles = 53248 B -> 2 CTAs/SM.
// Epilogue reuses ALL smem as float[128][100] staging (51200 B).
extern __shared__ uint32_t sm[];

__global__ __launch_bounds__(256, 2) void fused_kernel(const float* __restrict__ x,
                                                       const float* __restrict__ bv,
                                                       float* __restrict__ out) {
    const int tid = threadIdx.x;
    const int lane = tid & 31;
    const int w = tid >> 5;
    const int nh = w & 1;   // n-half within the tile
    const int tp = w >> 1;  // tile slot 0..3
    const int g = lane >> 2, tc = lane & 3;

    uint32_t* Xhi = sm + tp * 3328;  // 2048 u32
    uint32_t* Ex = Xhi + 2048;       // 1280 u32: Spar then Pbuf

    const int tile = blockIdx.x * 4 + tp;
    const int n = tile >> 8;
    const int t = tile & 255;
    const long xbase = (long)n * 819200 + (long)t * 25;

    // ---- x tile -> fp16 image; pair splits block range (lane = row v) ----
    // X-image: [row][16B block b], swizzled: uint4 idx = row*16 + (b ^ (row&7)).
    {
        const bool valid = lane < 25;
        const float* xr = x + xbase + lane;
        uint4* Xhi4 = (uint4*)Xhi;
        const int f = lane & 7;
#pragma unroll 2
        for (int j = 0; j < 8; j++) {
            const int b = nh * 8 + j;  // 16B block = 4 u32 = 8 channels
            const float* xb = xr + (long)b * 51200;
            uint4 hi4;
            float x0, x1;
            x0 = valid ? __ldcs(xb + 0) : 0.f;
            x1 = valid ? __ldcs(xb + 6400) : 0.f;
            hi4.x = packh(x0, x1);
            x0 = valid ? __ldcs(xb + 12800) : 0.f;
            x1 = valid ? __ldcs(xb + 19200) : 0.f;
            hi4.y = packh(x0, x1);
            x0 = valid ? __ldcs(xb + 25600) : 0.f;
            x1 = valid ? __ldcs(xb + 32000) : 0.f;
            hi4.z = packh(x0, x1);
            x0 = valid ? __ldcs(xb + 38400) : 0.f;
            x1 = valid ? __ldcs(xb + 44800) : 0.f;
            hi4.w = packh(x0, x1);
            Xhi4[lane * 16 + (b ^ f)] = hi4;
        }
    }
    __syncthreads();

    const uint32_t XhiA = smem_u32(Xhi);
    const uint32_t ExA = XhiA + 8192;

    // A-frag LDSM components (both m-tiles)
    const int rA = (lane & 7) + 8 * ((lane >> 3) & 1);
    const uint32_t Aoff0 = (uint32_t)rA * 256;  // rows 0-15
    const uint32_t Aoff1 = Aoff0 + 16 * 256;    // rows 16-31
    const int fA = rA & 7;
    const int kbA = (lane >> 4) & 1;

    // ---- G = X*M (+u), single-pass fp16, m32 x n64 (this warp's n-half) ----
    float acc[2][8][4];
#pragma unroll
    for (int mt = 0; mt < 2; mt++)
#pragma unroll
        for (int nt = 0; nt < 8; nt++)
#pragma unroll
            for (int q = 0; q < 4; q++) acc[mt][nt][q] = 0.f;
    {
        const uint4* BpH = (const uint4*)g_Wf + lane;
#pragma unroll
        for (int ks = 0; ks < 8; ks++) {
            const uint32_t koff = (uint32_t)(((2 * ks + kbA) ^ fA) << 4);
            uint32_t a0[4], a1[4];
            LDSM_X4(a0[0], a0[1], a0[2], a0[3], XhiA + Aoff0 + koff);
            LDSM_X4(a1[0], a1[1], a1[2], a1[3], XhiA + Aoff1 + koff);
#pragma unroll
            for (int nt2 = 0; nt2 < 4; nt2++) {
                const uint4 bh = __ldg(BpH + (ks * 8 + 4 * nh + nt2) * 32);
                MMA_F16(acc[0][2 * nt2], a0, bh.x, bh.y);
                MMA_F16(acc[0][2 * nt2 + 1], a0, bh.z, bh.w);
                MMA_F16(acc[1][2 * nt2], a1, bh.x, bh.y);
                MMA_F16(acc[1][2 * nt2 + 1], a1, bh.z, bh.w);
            }
        }
    }

    // ---- +u, convert G into fp16 A-fragments (k-chunks 4nh..4nh+3) ----
    uint32_t GhA[2][4][4];
#pragma unroll
    for (int kkl = 0; kkl < 4; kkl++) {
        const int kk = 4 * nh + kkl;
        float2 ua = *(const float2*)(g_u + 16 * kk + 2 * tc);
        float2 ub = *(const float2*)(g_u + 16 * kk + 8 + 2 * tc);
#pragma unroll
        for (int mt = 0; mt < 2; mt++) {
            GhA[mt][kkl][0] = packh(acc[mt][2 * kkl][0] + ua.x, acc[mt][2 * kkl][1] + ua.y);
            GhA[mt][kkl][1] = packh(acc[mt][2 * kkl][2] + ua.x, acc[mt][2 * kkl][3] + ua.y);
            GhA[mt][kkl][2] =
                packh(acc[mt][2 * kkl + 1][0] + ub.x, acc[mt][2 * kkl + 1][1] + ub.y);
            GhA[mt][kkl][3] =
                packh(acc[mt][2 * kkl + 1][2] + ub.x, acc[mt][2 * kkl + 1][3] + ub.y);
        }
    }

    // ---- S partial = G(:, k-half) * X(:, k-half)^T, single-pass, m32 x n32 ----
    const int rS = (lane & 7) + 8 * ((lane >> 4) & 1);
    const uint32_t SoffRow1 = (uint32_t)rS * 256;
    const uint32_t SoffRow2 = SoffRow1 + 16 * 256;
    const int fS = lane & 7;
    const int kbS = (lane >> 3) & 1;

    float S[2][4][4];
#pragma unroll
    for (int mt = 0; mt < 2; mt++)
#pragma unroll
        for (int nt = 0; nt < 4; nt++)
#pragma unroll
            for (int q = 0; q < 4; q++) S[mt][nt][q] = 0.f;
#pragma unroll
    for (int ksl = 0; ksl < 4; ksl++) {
        const int kg = 4 * nh + ksl;
        const uint32_t off = (uint32_t)(((2 * kg + kbS) ^ fS) << 4);
        uint32_t b0, b1, b2, b3, c0, c1, c2, c3;
        LDSM_X4(b0, b1, b2, b3, XhiA + SoffRow1 + off);
        LDSM_X4(c0, c1, c2, c3, XhiA + SoffRow2 + off);
        MMA_F16(S[0][0], GhA[0][ksl], b0, b1);
        MMA_F16(S[0][1], GhA[0][ksl], b2, b3);
        MMA_F16(S[0][2], GhA[0][ksl], c0, c1);
        MMA_F16(S[0][3], GhA[0][ksl], c2, c3);
        MMA_F16(S[1][0], GhA[1][ksl], b0, b1);
        MMA_F16(S[1][1], GhA[1][ksl], b2, b3);
        MMA_F16(S[1][2], GhA[1][ksl], c0, c1);
        MMA_F16(S[1][3], GhA[1][ksl], c2, c3);
    }

    // ---- exchange: store partial for the OTHER m-half; keep own ----
    {
        float* Sp = (float*)Ex + nh * 544;  // [16 rows][stride 34]
        const int mto = 1 - nh;
#pragma unroll
        for (int nt = 0; nt < 4; nt++) {
            const int w0 = 8 * nt + 2 * tc;
            *(float2*)&Sp[g * 34 + w0] = make_float2(S[mto][nt][0], S[mto][nt][1]);
            *(float2*)&Sp[(g + 8) * 34 + w0] = make_float2(S[mto][nt][2], S[mto][nt][3]);
        }
    }
    PAIR_BAR();
    float Sv[4][4];
    {
        const float* Sq = (float*)Ex + (1 - nh) * 544;
#pragma unroll
        for (int nt = 0; nt < 4; nt++) {
            const int w0 = 8 * nt + 2 * tc;
            float2 p0 = *(const float2*)&Sq[g * 34 + w0];
            float2 p1 = *(const float2*)&Sq[(g + 8) * 34 + w0];
            Sv[nt][0] = S[nh][nt][0] + p0.x;
            Sv[nt][1] = S[nh][nt][1] + p0.y;
            Sv[nt][2] = S[nh][nt][2] + p1.x;
            Sv[nt][3] = S[nh][nt][3] + p1.y;
        }
    }

    // ---- bias + mask + softmax on own rows (v = 16nh + g, +8) ----
    {
        const int v0 = 16 * nh + g;
        const int v1c = (v0 + 8 < 25) ? v0 + 8 : 24;  // index clamp only
#pragma unroll
        for (int nt = 0; nt < 4; nt++) {
            const int w0 = 8 * nt + 2 * tc, w1 = w0 + 1;
            if (w0 < 25) {
                Sv[nt][0] += g_bias[v0 * 26 + w0];
                Sv[nt][2] += g_bias[v1c * 26 + w0];
            } else {
                Sv[nt][0] = -1e30f;
                Sv[nt][2] = -1e30f;
            }
            if (w1 < 25) {
                Sv[nt][1] += g_bias[v0 * 26 + w1];
                Sv[nt][3] += g_bias[v1c * 26 + w1];
            } else {
                Sv[nt][1] = -1e30f;
                Sv[nt][3] = -1e30f;
            }
        }
    }
#pragma unroll
    for (int h = 0; h < 2; h++) {
        float mx = -1e30f;
#pragma unroll
        for (int nt = 0; nt < 4; nt++)
            mx = fmaxf(mx, fmaxf(Sv[nt][2 * h], Sv[nt][2 * h + 1]));
        mx = fmaxf(mx, __shfl_xor_sync(0xffffffffu, mx, 1));
        mx = fmaxf(mx, __shfl_xor_sync(0xffffffffu, mx, 2));
        float sum = 0.f;
#pragma unroll
        for (int nt = 0; nt < 4; nt++) {
            float e0 = __expf(Sv[nt][2 * h] - mx);
            float e1 = __expf(Sv[nt][2 * h + 1] - mx);
            Sv[nt][2 * h] = e0;
            Sv[nt][2 * h + 1] = e1;
            sum += e0 + e1;
        }
        sum += __shfl_xor_sync(0xffffffffu, sum, 1);
        sum += __shfl_xor_sync(0xffffffffu, sum, 2);
        float inv = __fdividef(1.f, sum);
#pragma unroll
        for (int nt = 0; nt < 4; nt++) {
            Sv[nt][2 * h] *= inv;
            Sv[nt][2 * h + 1] *= inv;
        }
    }
    PAIR_BAR();  // Spar reads done; Ex reusable as Pbuf

    // ---- P -> Pbuf fp16 [32 rows v][stride 40 halfs] ----
    {
        uint32_t* Pb = Ex;
#pragma unroll
        for (int nt = 0; nt < 4; nt++) {
            Pb[(16 * nh + g) * 20 + 4 * nt + tc] = packh(Sv[nt][0], Sv[nt][1]);
            Pb[(16 * nh + g + 8) * 20 + 4 * nt + tc] = packh(Sv[nt][2], Sv[nt][3]);
        }
    }

    // ---- V = X * wv^T, single-pass fp16, m32 x n64 (this warp's o-half) ----
    float accV[2][8][4];
#pragma unroll
    for (int mt = 0; mt < 2; mt++)
#pragma unroll
        for (int nt = 0; nt < 8; nt++)
#pragma unroll
            for (int q = 0; q < 4; q++) accV[mt][nt][q] = 0.f;
    {
        const uint4* Bp = (const uint4*)g_Wf + 4096 + lane;
#pragma unroll
        for (int ks = 0; ks < 8; ks++) {
            const uint32_t koff = (uint32_t)(((2 * ks + kbA) ^ fA) << 4);
            uint32_t a0[4], a1[4];
            LDSM_X4(a0[0], a0[1], a0[2], a0[3], XhiA + Aoff0 + koff);
            LDSM_X4(a1[0], a1[1], a1[2], a1[3], XhiA + Aoff1 + koff);
#pragma unroll
            for (int nt2 = 0; nt2 < 4; nt2++) {
                const uint4 b = __ldg(Bp + (ks * 8 + 4 * nh + nt2) * 32);
                MMA_F16(accV[0][2 * nt2], a0, b.x, b.y);
                MMA_F16(accV[0][2 * nt2 + 1], a0, b.z, b.w);
                MMA_F16(accV[1][2 * nt2], a1, b.x, b.y);
                MMA_F16(accV[1][2 * nt2 + 1], a1, b.z, b.w);
            }
        }
    }
    PAIR_BAR();  // Pbuf visible to pair; both warps done reading Xhi

    // ---- PA: LDSM P A-fragments for full m32 (reads Pbuf in Ex) ----
    uint32_t PA[2][2][4];
    {
        const int rowP = (lane & 7) + 8 * ((lane >> 3) & 1);
        const uint32_t blkk = (uint32_t)((lane >> 4) & 1);
#pragma unroll
        for (int mt = 0; mt < 2; mt++)
#pragma unroll
            for (int ks2 = 0; ks2 < 2; ks2++) {
                LDSM_X4(PA[mt][ks2][0], PA[mt][ks2][1], PA[mt][ks2][2], PA[mt][ks2][3],
                        ExA + (uint32_t)(16 * mt + rowP) * 80 + (2 * ks2 + blkk) * 16);
            }
    }
    PAIR_BAR();  // both warps' PA reads done before Vso overwrites Pbuf start

    // ---- Vso overlay: V^T fp16 [o][w], stride 40 halfs (spans Xhi + Ex head) ----
    unsigned short* Vso = (unsigned short*)Xhi;  // 10240 B <= 13312 B tile region
#pragma unroll
    for (int mt = 0; mt < 2; mt++)
#pragma unroll
        for (int nt = 0; nt < 8; nt++) {
            const int o0 = 64 * nh + 8 * nt + 2 * tc, r0 = 16 * mt + g;
            Vso[o0 * 40 + r0] = f2h(accV[mt][nt][0]);
            Vso[(o0 + 1) * 40 + r0] = f2h(accV[mt][nt][1]);
            Vso[o0 * 40 + r0 + 8] = f2h(accV[mt][nt][2]);
            Vso[(o0 + 1) * 40 + r0 + 8] = f2h(accV[mt][nt][3]);
        }
    PAIR_BAR();

    // ---- PV: out = P*V + bv, m32 x o-half (k = w padded to 32, pads exact zeros) ----
    float accO[2][8][4];
#pragma unroll
    for (int nt = 0; nt < 8; nt++) {
        float2 bb = *(const float2*)(bv + 64 * nh + 8 * nt + 2 * tc);
#pragma unroll
        for (int mt = 0; mt < 2; mt++) {
            accO[mt][nt][0] = bb.x;
            accO[mt][nt][1] = bb.y;
            accO[mt][nt][2] = bb.x;
            accO[mt][nt][3] = bb.y;
        }
    }
    {
        const uint32_t* VsoU = (const uint32_t*)Vso;
#pragma unroll
        for (int ks2 = 0; ks2 < 2; ks2++) {
#pragma unroll
            for (int nt = 0; nt < 8; nt++) {
                const int orow = (64 * nh + 8 * nt + g) * 20;
                uint32_t b0 = VsoU[orow + 8 * ks2 + tc];
                uint32_t b1 = VsoU[orow + 8 * ks2 + 4 + tc];
                MMA_F16(accO[0][nt], PA[0][ks2], b0, b1);
                MMA_F16(accO[1][nt], PA[1][ks2], b0, b1);
            }
        }
    }
    __syncthreads();  // ALL warps done with per-tile smem

    // ---- CTA-wide staging: OA[o][100] floats (4 consecutive t, 25 v each) ----
    float* OA = (float*)sm;  // 128 * 100 * 4 = 51200 B
    {
        const int colb = tp * 25;
#pragma unroll
        for (int mt = 0; mt < 2; mt++) {
            const int v0 = 16 * mt + g;
            const int v1 = v0 + 8;
#pragma unroll
            for (int nt = 0; nt < 8; nt++) {
                const int o0 = 64 * nh + 8 * nt + 2 * tc;
                OA[o0 * 100 + colb + v0] = accO[mt][nt][0];
                OA[(o0 + 1) * 100 + colb + v0] = accO[mt][nt][1];
                if (v1 < 25) {
                    OA[o0 * 100 + colb + v1] = accO[mt][nt][2];
                    OA[(o0 + 1) * 100 + colb + v1] = accO[mt][nt][3];
                }
            }
        }
    }
    __syncthreads();

    // ---- vectorized store: out[n][o][t0..t0+3][0..24] = 100 floats/row, float4 ----
    {
        const int tile0 = blockIdx.x * 4;
        const int n0 = tile0 >> 8;
        const int t0 = tile0 & 255;
        float4* out4 = (float4*)(out + (long)n0 * 819200 + (long)t0 * 25);
        int i = tid;
        int row = tid / 25;
        int c = tid - row * 25;
#pragma unroll 1
        for (int j = 0; j < 13; j++) {
            if (i < 3200) {
                float4 vle = *(const float4*)(OA + row * 100 + 4 * c);
                __stcs(out4 + row * 1600 + c, vle);
            }
            i += 256;
            c += 6;
            row += 10;
            if (c >= 25) {
                c -= 25;
                row += 1;
            }
        }
    }
}

extern "C" void kernel_launch(void* const* d_in, const int* in_sizes, int n_in,
                              void* d_out, int out_size) {
    (void)in_sizes; (void)n_in; (void)out_size;
    const float* x = (const float*)d_in[0];
    const float* wq = (const float*)d_in[1];
    const float* bq = (const float*)d_in[2];
    const float* wk = (const float*)d_in[3];
    // d_in[4] = bk: softmax-invariant (row-constant), unused
    const float* wv = (const float*)d_in[5];
    const float* bv = (const float*)d_in[6];
    const float* be = (const float*)d_in[7];
    const int* hop = (const int*)d_in[8];

    cudaFuncSetAttribute(fused_kernel, cudaFuncAttributeMaxDynamicSharedMemorySize,
                         53248);

    precompute_kernel<<<130, 128>>>(wq, bq, wk, wv, be, hop);
    fused_kernel<<<NT_TOTAL / 4, 256, 53248>>>(x, bv, (float*)d_out);
}